// round 2
// baseline (speedup 1.0000x reference)
#include <cuda_runtime.h>
#include <math.h>

#define B_   64
#define T_   256
#define ET_  1024
#define U_   512
#define V_   46
#define NG_  2048           // 4*U
#define KSPLIT 8
#define KCH  128            // 1024 / KSPLIT
#define NCTA 128
#define NTHR 256

// ------------------------- persistent device state -------------------------
__device__ float g_h1[B_*U_];
__device__ float g_c1[B_*U_];
__device__ float g_h2[B_*U_];
__device__ float g_c2[B_*U_];
__device__ float g_ctx[B_*U_];

__device__ float g_Wc1[1024*NG_];   // rows 0..511: W1[0:512]+U1 ; rows 512..1023: W1[513:1025]
__device__ float g_w1y[NG_];        // W1 row 512 (multiplies scalar y_t)
__device__ float g_Wc2[1024*NG_];   // rows 0..511: W2 ; rows 512..1023: U2
__device__ float g_WdT[V_*1024];    // transposed decoder weights

__device__ float g_Zp[KSPLIT*B_*NG_];   // K-split GEMM partials

__device__ float g_pm[B_*64];           // attention partial max
__device__ float g_ps[B_*64];           // attention partial sum
__device__ float g_pctx[B_*64*U_];      // attention partial (unnorm) context

// grid barrier state
__device__ unsigned int g_bar_count = 0;
__device__ unsigned int g_bar_gen   = 0;

// ------------------------------ shared union -------------------------------
union SmemU {
    struct { float As[8][64]; float Bs[8][128]; } g;       // gemm
    struct { float st[4][1024]; float lg[4][48]; } d;      // decoder
    float wgt[64];                                         // combine
};

// ------------------------------ grid barrier -------------------------------
__device__ __forceinline__ void grid_barrier()
{
    __syncthreads();
    if (threadIdx.x == 0) {
        unsigned int gen = *(volatile unsigned int*)&g_bar_gen;
        __threadfence();
        unsigned int ticket = atomicAdd(&g_bar_count, 1u);
        if (ticket == gridDim.x - 1) {
            atomicExch(&g_bar_count, 0u);
            __threadfence();
            *(volatile unsigned int*)&g_bar_gen = gen + 1u;
        } else {
            while (*(volatile unsigned int*)&g_bar_gen == gen) {
                __nanosleep(64);
            }
        }
        __threadfence();
    }
    __syncthreads();
}

// ------------------------------ LSTM GEMM phase ----------------------------
// Z_partial[ks] = A_slice @ W_slice.  128 CTAs = 16 col-tiles x 8 K-splits.
// Tile 64(M) x 128(N), K chunk 128.  Thread: 8 rows x 4 cols.
__device__ __forceinline__ void gemm_phase(int which, SmemU& sm)
{
    const float* __restrict__ S1 = which ? g_ctx : g_h1;
    const float* __restrict__ S2 = which ? g_h2  : g_ctx;
    const float* __restrict__ W  = which ? g_Wc2 : g_Wc1;

    const int nt = blockIdx.x & 15;      // col tile 0..15
    const int ks = blockIdx.x >> 4;      // K split 0..7
    const int kg = ks * KCH;             // offset in combined 1024-row W
    const float* __restrict__ A = (kg < 512) ? S1 : S2;
    const int kbase = kg & 511;          // offset within 512-wide source
    const int ncol0 = nt * 128;

    const int tid = threadIdx.x;
    const int ty  = tid >> 5;            // 0..7 -> rows ty*8
    const int tx  = tid & 31;            // cols tx + 32*j

    float acc[8][4];
#pragma unroll
    for (int r = 0; r < 8; ++r)
#pragma unroll
        for (int c = 0; c < 4; ++c) acc[r][c] = 0.f;

    for (int kt = 0; kt < KCH; kt += 8) {
        // stage A: 64 rows x 8 k (transposed into As[k][row])
        if (tid < 128) {
            int row = tid & 63;
            int kh  = (tid >> 6) * 4;    // 0 or 4
            float4 a = *(const float4*)(A + row*U_ + kbase + kt + kh);
            sm.g.As[kh+0][row] = a.x;
            sm.g.As[kh+1][row] = a.y;
            sm.g.As[kh+2][row] = a.z;
            sm.g.As[kh+3][row] = a.w;
        }
        // stage B: 8 k x 128 cols
        {
            int krB = tid >> 5;          // 0..7
            int cB  = (tid & 31) * 4;
            *(float4*)&sm.g.Bs[krB][cB] =
                *(const float4*)(W + (size_t)(kg + kt + krB)*NG_ + ncol0 + cB);
        }
        __syncthreads();

#pragma unroll
        for (int k = 0; k < 8; ++k) {
            float4 a0 = *(const float4*)&sm.g.As[k][ty*8];
            float4 a1 = *(const float4*)&sm.g.As[k][ty*8 + 4];
            float ar[8] = {a0.x,a0.y,a0.z,a0.w,a1.x,a1.y,a1.z,a1.w};
            float br[4];
#pragma unroll
            for (int j = 0; j < 4; ++j) br[j] = sm.g.Bs[k][tx + 32*j];
#pragma unroll
            for (int r = 0; r < 8; ++r)
#pragma unroll
                for (int c = 0; c < 4; ++c) acc[r][c] += ar[r]*br[c];
        }
        __syncthreads();
    }

    float* zp = g_Zp + ks*(B_*NG_);
#pragma unroll
    for (int r = 0; r < 8; ++r) {
        float* op = zp + (size_t)(ty*8 + r)*NG_ + ncol0 + tx;
#pragma unroll
        for (int c = 0; c < 4; ++c) op[32*c] = acc[r][c];
    }
}

// ------------------------------ LSTM gate phase ----------------------------
__device__ __forceinline__ void gate_phase(int which, const float* __restrict__ bias,
                                           const float* __restrict__ y, int t)
{
    int idx = blockIdx.x*NTHR + threadIdx.x;       // 0..32767 == B*U
    int b = idx >> 9;
    int u = idx & (U_-1);

    float zi=0.f, zf=0.f, zg=0.f, zo=0.f;
#pragma unroll
    for (int p = 0; p < KSPLIT; ++p) {
        const float* z = g_Zp + p*(B_*NG_) + (size_t)b*NG_;
        zi += z[u]; zf += z[512+u]; zg += z[1024+u]; zo += z[1536+u];
    }
    zi += bias[u]; zf += bias[512+u]; zg += bias[1024+u]; zo += bias[1536+u];

    if (!which) {
        float yv = y[b*T_ + t];
        zi += yv*g_w1y[u]; zf += yv*g_w1y[512+u]; zg += yv*g_w1y[1024+u]; zo += yv*g_w1y[1536+u];
    }

    float* hS = which ? g_h2 : g_h1;
    float* cS = which ? g_c2 : g_c1;

    float si = 1.f/(1.f+expf(-zi));
    float sf = 1.f/(1.f+expf(-zf));
    float so = 1.f/(1.f+expf(-zo));
    float cn = sf*cS[idx] + si*tanhf(zg);
    cS[idx] = cn;
    hS[idx] = so*tanhf(cn);
}

// ---------------------------- attention (flash) ----------------------------
// 512 units (b, slice-of-128-keys); each CTA processes 4 units.
// 8 warps/unit, warp owns 16 keys, online softmax, h row read once.
__device__ __forceinline__ void attn_phase(const float* __restrict__ henc)
{
    const int w    = threadIdx.x >> 5;
    const int lane = threadIdx.x & 31;

    for (int uu = 0; uu < 4; ++uu) {
        const int unit  = blockIdx.x*4 + uu;
        const int b     = unit >> 3;
        const int slice = unit & 7;

        const float* h1b = g_h1 + b*U_;
        float4 q[4];
#pragma unroll
        for (int i = 0; i < 4; ++i)
            q[i] = *(const float4*)(h1b + i*128 + lane*4);

        float m = -INFINITY, s = 0.f;
        float4 acc[4];
#pragma unroll
        for (int i = 0; i < 4; ++i) acc[i] = make_float4(0.f,0.f,0.f,0.f);

        const int t0 = slice*128 + w*16;
        const float* hb = henc + (size_t)b*ET_*U_;

#pragma unroll 4
        for (int tt = 0; tt < 16; ++tt) {
            const float* hr = hb + (size_t)(t0+tt)*U_;
            float4 k0 = *(const float4*)(hr + 0*128 + lane*4);
            float4 k1 = *(const float4*)(hr + 1*128 + lane*4);
            float4 k2 = *(const float4*)(hr + 2*128 + lane*4);
            float4 k3 = *(const float4*)(hr + 3*128 + lane*4);

            float d = q[0].x*k0.x + q[0].y*k0.y + q[0].z*k0.z + q[0].w*k0.w
                    + q[1].x*k1.x + q[1].y*k1.y + q[1].z*k1.z + q[1].w*k1.w
                    + q[2].x*k2.x + q[2].y*k2.y + q[2].z*k2.z + q[2].w*k2.w
                    + q[3].x*k3.x + q[3].y*k3.y + q[3].z*k3.z + q[3].w*k3.w;
#pragma unroll
            for (int o = 16; o; o >>= 1) d += __shfl_xor_sync(0xffffffffu, d, o);

            float mn = fmaxf(m, d);
            float sc = expf(m - mn);     // 0 on first iter (m = -inf)
            float p  = expf(d - mn);
            s = s*sc + p;
            acc[0].x = acc[0].x*sc + p*k0.x; acc[0].y = acc[0].y*sc + p*k0.y;
            acc[0].z = acc[0].z*sc + p*k0.z; acc[0].w = acc[0].w*sc + p*k0.w;
            acc[1].x = acc[1].x*sc + p*k1.x; acc[1].y = acc[1].y*sc + p*k1.y;
            acc[1].z = acc[1].z*sc + p*k1.z; acc[1].w = acc[1].w*sc + p*k1.w;
            acc[2].x = acc[2].x*sc + p*k2.x; acc[2].y = acc[2].y*sc + p*k2.y;
            acc[2].z = acc[2].z*sc + p*k2.z; acc[2].w = acc[2].w*sc + p*k2.w;
            acc[3].x = acc[3].x*sc + p*k3.x; acc[3].y = acc[3].y*sc + p*k3.y;
            acc[3].z = acc[3].z*sc + p*k3.z; acc[3].w = acc[3].w*sc + p*k3.w;
            m = mn;
        }

        const int pidx = slice*8 + w;
        if (lane == 0) { g_pm[b*64 + pidx] = m; g_ps[b*64 + pidx] = s; }
        float* pc = g_pctx + ((size_t)(b*64 + pidx))*U_;
#pragma unroll
        for (int i = 0; i < 4; ++i)
            *(float4*)(pc + i*128 + lane*4) = acc[i];
    }
}

// Deterministic merge of the 64 per-warp partials into g_ctx.  CTAs 0..63.
__device__ __forceinline__ void combine_phase(SmemU& sm)
{
    if (blockIdx.x >= B_) return;
    const int b   = blockIdx.x;
    const int tid = threadIdx.x;

    float M = -INFINITY;
#pragma unroll
    for (int p = 0; p < 64; ++p) M = fmaxf(M, g_pm[b*64 + p]);
    if (tid < 64) sm.wgt[tid] = expf(g_pm[b*64 + tid] - M);
    __syncthreads();

    float st = 0.f;
#pragma unroll
    for (int p = 0; p < 64; ++p) st += g_ps[b*64 + p]*sm.wgt[p];
    float inv = 1.f/st;

#pragma unroll
    for (int hh = 0; hh < 2; ++hh) {
        int d = tid + hh*256;
        float a = 0.f;
        const float* pc = g_pctx + (size_t)b*64*U_ + d;
#pragma unroll
        for (int p = 0; p < 64; ++p) a += pc[(size_t)p*U_]*sm.wgt[p];
        g_ctx[b*U_ + d] = a*inv;
    }
}

// ------------------------------- decoder -----------------------------------
// CTAs 0..15 (4 b each).  Warp (bi,half) computes 23 logits, then softmax.
__device__ __forceinline__ void decoder_phase(const float* __restrict__ bd, int t,
                                              float* __restrict__ out, SmemU& sm)
{
    if (blockIdx.x >= 16) return;
    const int b0  = blockIdx.x*4;
    const int tid = threadIdx.x;

    for (int idx = tid; idx < 4*1024; idx += NTHR) {
        int bi = idx >> 10, k = idx & 1023;
        sm.d.st[bi][k] = (k < 512) ? g_h2[(b0+bi)*U_ + k] : g_ctx[(b0+bi)*U_ + k - 512];
    }
    __syncthreads();

    const int w = tid >> 5, lane = tid & 31;
    const int bi = w >> 1;
    const int vh = (w & 1)*23;

    for (int vv = 0; vv < 23; ++vv) {
        int v = vh + vv;
        const float* wrow = g_WdT + (size_t)v*1024;
        float a = 0.f;
#pragma unroll 8
        for (int k = lane; k < 1024; k += 32) a += sm.d.st[bi][k]*wrow[k];
#pragma unroll
        for (int o = 16; o; o >>= 1) a += __shfl_xor_sync(0xffffffffu, a, o);
        if (lane == 0) sm.d.lg[bi][v] = a + bd[v];
    }
    __syncthreads();

    if (w < 4) {
        float x0 = (lane      < V_) ? sm.d.lg[w][lane]      : -INFINITY;
        float x1 = (lane + 32 < V_) ? sm.d.lg[w][lane + 32] : -INFINITY;
        float mx = fmaxf(x0, x1);
#pragma unroll
        for (int o = 16; o; o >>= 1) mx = fmaxf(mx, __shfl_xor_sync(0xffffffffu, mx, o));
        float e0 = (lane      < V_) ? expf(x0 - mx) : 0.f;
        float e1 = (lane + 32 < V_) ? expf(x1 - mx) : 0.f;
        float ss = e0 + e1;
#pragma unroll
        for (int o = 16; o; o >>= 1) ss += __shfl_xor_sync(0xffffffffu, ss, o);
        float invs = 1.f/ss;
        float* op = out + ((size_t)(b0 + w)*T_ + t)*V_;
        if (lane      < V_) op[lane]      = e0*invs;
        if (lane + 32 < V_) op[lane + 32] = e1*invs;
    }
    __syncthreads();
}

// --------------------------- persistent kernel -----------------------------
__global__ void __launch_bounds__(NTHR, 1)
speller_persistent(const float* __restrict__ h,  const float* __restrict__ y,
                   const float* __restrict__ W1, const float* __restrict__ U1,
                   const float* __restrict__ b1, const float* __restrict__ W2,
                   const float* __restrict__ U2, const float* __restrict__ b2,
                   const float* __restrict__ Wd, const float* __restrict__ bd,
                   float* __restrict__ out)
{
    __shared__ SmemU sm;
    const int gtid = blockIdx.x*NTHR + threadIdx.x;     // 0..32767

    // ---- prologue: zero state + prefold weights ----
    g_h1[gtid]=0.f; g_c1[gtid]=0.f; g_h2[gtid]=0.f; g_c2[gtid]=0.f; g_ctx[gtid]=0.f;

    for (int idx = gtid; idx < 1024*NG_; idx += NCTA*NTHR) {
        int k = idx >> 11;
        int n = idx & (NG_-1);
        g_Wc1[idx] = (k < 512) ? (W1[idx] + U1[idx]) : W1[(size_t)(k+1)*NG_ + n];
        g_Wc2[idx] = (k < 512) ? W2[idx] : U2[idx - 512*NG_];
    }
    if (gtid < NG_) g_w1y[gtid] = W1[(size_t)512*NG_ + gtid];
    for (int idx = gtid; idx < V_*1024; idx += NCTA*NTHR) {
        g_WdT[idx] = Wd[(size_t)(idx & 1023)*V_ + (idx >> 10)];
    }
    grid_barrier();

    // ---- 256 decode steps ----
    for (int t = 0; t < T_; ++t) {
        gemm_phase(0, sm);          grid_barrier();
        gate_phase(0, b1, y, t);    grid_barrier();
        attn_phase(h);              grid_barrier();
        combine_phase(sm);          grid_barrier();
        gemm_phase(1, sm);          grid_barrier();
        gate_phase(1, b2, y, t);    grid_barrier();
        decoder_phase(bd, t, out, sm);
        // no barrier: decoder CTAs (0..15) precede their own next-step GEMM
        // tile, and the post-GEMM barrier orders everything that could
        // conflict (combine's ctx write is 4 barriers downstream).
    }
}

// ------------------------------- launcher ----------------------------------
extern "C" void kernel_launch(void* const* d_in, const int* in_sizes, int n_in,
                              void* d_out, int out_size)
{
    (void)in_sizes; (void)n_in; (void)out_size;
    const float* h  = (const float*)d_in[0];
    const float* y  = (const float*)d_in[1];
    const float* W1 = (const float*)d_in[2];
    const float* U1 = (const float*)d_in[3];
    const float* b1 = (const float*)d_in[4];
    const float* W2 = (const float*)d_in[5];
    const float* U2 = (const float*)d_in[6];
    const float* b2 = (const float*)d_in[7];
    const float* Wd = (const float*)d_in[8];
    const float* bd = (const float*)d_in[9];
    float* out = (float*)d_out;

    speller_persistent<<<NCTA, NTHR>>>(h, y, W1, U1, b1, W2, U2, b2, Wd, bd, out);
}

// round 4
// speedup vs baseline: 1.4547x; 1.4547x over previous
#include <cuda_runtime.h>
#include <cuda_fp16.h>
#include <math.h>

#define B_   64
#define T_   256
#define ET_  1024
#define U_   512
#define V_   46
#define NG_  2048
#define NCTA 128
#define NTHR 256

// ------------------------- persistent device state -------------------------
__device__ float g_h1[2][B_*U_];
__device__ float g_c1[2][B_*U_];
__device__ float g_h2[2][B_*U_];
__device__ float g_c2[2][B_*U_];
__device__ float g_h1T[2][U_*B_];
__device__ float g_h2T[2][U_*B_];
__device__ float g_ctx[B_*U_];
__device__ float g_ctxT[U_*B_];

__device__ __half g_hh[(size_t)B_*ET_*U_];     // 67 MB fp16 copy of h

__device__ float g_Wt1[(size_t)NCTA*1024*16];  // per-CTA folded weights layer1
__device__ float g_Wt2[(size_t)NCTA*1024*16];  // per-CTA folded weights layer2
__device__ float g_w1y[NG_];
__device__ float g_WdT[V_*1024];

__device__ float g_pm[NCTA];                   // attention partial max
__device__ float g_ps[NCTA];                   // attention partial sum
__device__ float g_pctx[NCTA][U_];             // attention partial (unnorm) ctx
__device__ float g_logits[B_*48];

__device__ unsigned int g_aflag[B_];           // monotonic pair tickets (attn)
__device__ unsigned int g_dflag[B_];           // monotonic pair tickets (decoder)
__device__ unsigned int g_bar_count = 0;
__device__ unsigned int g_bar_gen   = 0;

// ------------------------------ shared memory ------------------------------
union SmemU {
    struct { float As[4][32][64]; float Ws[4][32][16]; } g;   // 40 KB gemm
    struct { float zb[4][64][16]; } z;                        // 16 KB (aliases As after sync)
    struct { __half Kt[32][520]; float sc[32]; float pp[32];
             float corr; float mrun; float srun; } a;         // ~33.6 KB attention
    struct { float st[1024]; } d;                             // 4 KB decoder
};

// ------------------------------ small helpers ------------------------------
__device__ __forceinline__ void fma2(unsigned long long& acc, unsigned long long a,
                                     unsigned long long w) {
    asm("fma.rn.f32x2 %0, %1, %2, %0;" : "+l"(acc) : "l"(a), "l"(w));
}
__device__ __forceinline__ unsigned long long dupf(float x) {
    unsigned long long r;
    asm("mov.b64 %0, {%1, %2};" : "=l"(r) : "f"(x), "f"(x));
    return r;
}
__device__ __forceinline__ float2 unpack2(unsigned long long a) {
    float2 r;
    asm("mov.b64 {%0, %1}, %2;" : "=f"(r.x), "=f"(r.y) : "l"(a));
    return r;
}
__device__ __forceinline__ float fsig(float x) {
    return __fdividef(1.f, 1.f + __expf(-x));
}
__device__ __forceinline__ float ftanh(float x) {
    return __fdividef(2.f, 1.f + __expf(-2.f*x)) - 1.f;
}

// ------------------------------ grid barrier -------------------------------
__device__ __forceinline__ void grid_barrier()
{
    __syncthreads();
    if (threadIdx.x == 0) {
        unsigned int gen = *(volatile unsigned int*)&g_bar_gen;
        __threadfence();
        unsigned int ticket = atomicAdd(&g_bar_count, 1u);
        if (ticket == gridDim.x - 1) {
            atomicExch(&g_bar_count, 0u);
            __threadfence();
            *(volatile unsigned int*)&g_bar_gen = gen + 1u;
        } else {
            while (*(volatile unsigned int*)&g_bar_gen == gen) { __nanosleep(64); }
        }
        __threadfence();
    }
    __syncthreads();
}

// -------------------------- fused GEMM + LSTM gate -------------------------
// CTA c owns u = c*4 .. c*4+3 (all 4 gates -> 16 output cols j = gate*4+uu).
// z[b][j] = sum_k AT(k)[b] * Wt[c][k][j],  K=1024 split 4-ways across thread
// groups; inner math uses packed fma.rn.f32x2 (b-pairs).
__device__ __forceinline__ void gemm_gate_phase(
    int layer, const float* __restrict__ AT0, const float* __restrict__ AT1,
    const float* __restrict__ Wt, const float* __restrict__ bias,
    const float* __restrict__ cin, float* __restrict__ hout,
    float* __restrict__ cout, float* __restrict__ hTout,
    const float* __restrict__ y, int t, SmemU& sm)
{
    const int cta = blockIdx.x;
    const int tid = threadIdx.x;
    const float* __restrict__ wbase = Wt + (size_t)cta*1024*16;

    const int g  = tid >> 6;           // k-group 0..3
    const int t6 = tid & 63;
    const int b0 = (t6 & 7) * 8;       // 8 batch rows
    const int jp = t6 >> 3;            // 0..7 -> j0 = jp*2
    const int j0 = jp * 2;

    unsigned long long acc[4][2];
#pragma unroll
    for (int p = 0; p < 4; ++p) { acc[p][0] = 0ull; acc[p][1] = 0ull; }

    for (int it = 0; it < 8; ++it) {
        // stage A: 4 groups x 32 k x 64 b
#pragma unroll
        for (int i = 0; i < 8; ++i) {
            int f  = tid + i*256;
            int gg = f >> 9;
            int kk = (f >> 4) & 31;
            int bb = (f & 15) * 4;
            int kg = gg*256 + it*32 + kk;
            const float* src = (kg < 512) ? (AT0 + (size_t)kg*64)
                                          : (AT1 + (size_t)(kg-512)*64);
            *(float4*)&sm.g.As[gg][kk][bb] = *(const float4*)(src + bb);
        }
        // stage W: 4 groups x 32 k x 16 j
#pragma unroll
        for (int i = 0; i < 2; ++i) {
            int f  = tid + i*256;
            int gg = f >> 7;
            int kk = (f >> 2) & 31;
            int j4 = (f & 3) * 4;
            int kg = gg*256 + it*32 + kk;
            *(float4*)&sm.g.Ws[gg][kk][j4] = *(const float4*)(wbase + (size_t)kg*16 + j4);
        }
        __syncthreads();

#pragma unroll 8
        for (int kk = 0; kk < 32; ++kk) {
            float2 w = *(const float2*)&sm.g.Ws[g][kk][j0];
            unsigned long long wxx = dupf(w.x);
            unsigned long long wyy = dupf(w.y);
            ulonglong2 a01 = *(const ulonglong2*)&sm.g.As[g][kk][b0];
            ulonglong2 a23 = *(const ulonglong2*)&sm.g.As[g][kk][b0+4];
            fma2(acc[0][0], a01.x, wxx);  fma2(acc[0][1], a01.x, wyy);
            fma2(acc[1][0], a01.y, wxx);  fma2(acc[1][1], a01.y, wyy);
            fma2(acc[2][0], a23.x, wxx);  fma2(acc[2][1], a23.x, wyy);
            fma2(acc[3][0], a23.y, wxx);  fma2(acc[3][1], a23.y, wyy);
        }
        __syncthreads();
    }

    // dump partials (zb aliases As; safe after the sync above)
#pragma unroll
    for (int p = 0; p < 4; ++p) {
        float2 z0 = unpack2(acc[p][0]);
        float2 z1 = unpack2(acc[p][1]);
        int b = b0 + 2*p;
        sm.z.zb[g][b  ][j0  ] = z0.x;
        sm.z.zb[g][b+1][j0  ] = z0.y;
        sm.z.zb[g][b  ][j0+1] = z1.x;
        sm.z.zb[g][b+1][j0+1] = z1.y;
    }
    __syncthreads();

    // gate: thread -> (b = tid&63, uu = tid>>6), u = cta*4+uu
    {
        const int b  = tid & 63;
        const int uu = tid >> 6;
        const int u  = cta*4 + uu;
        float z[4];
#pragma unroll
        for (int gate = 0; gate < 4; ++gate) {
            int j = gate*4 + uu;
            float s = sm.z.zb[0][b][j] + sm.z.zb[1][b][j]
                    + sm.z.zb[2][b][j] + sm.z.zb[3][b][j];
            s += bias[gate*512 + u];
            z[gate] = s;
        }
        if (layer == 0) {
            float yv = y[b*T_ + t];
#pragma unroll
            for (int gate = 0; gate < 4; ++gate) z[gate] += yv * g_w1y[gate*512 + u];
        }
        float si = fsig(z[0]);
        float sf = fsig(z[1]);
        float tg = ftanh(z[2]);
        float so = fsig(z[3]);
        float cn = sf * cin[b*U_ + u] + si * tg;
        cout[b*U_ + u]  = cn;
        float hn = so * ftanh(cn);
        hout[b*U_ + u]  = hn;
        hTout[u*B_ + b] = hn;
    }
    __syncthreads();
}

// ---------------------------- attention (flash) ----------------------------
// CTA pair per b: cta = b*2 + half; each handles 512 keys in 16 tiles of 32.
__device__ __forceinline__ void attn_phase(const float* __restrict__ h1o, SmemU& sm,
                                           __shared__ int* s_ticket)
{
    const int cta  = blockIdx.x;
    const int tid  = threadIdx.x;
    const int lane = tid & 31;
    const int w    = tid >> 5;
    const int b    = cta >> 1;
    const int half = cta & 1;

    // q slices: d = j*64 + lane*2
    float2 q2[8];
    const float* h1b = h1o + b*U_;
#pragma unroll
    for (int j = 0; j < 8; ++j)
        q2[j] = *(const float2*)(h1b + j*64 + lane*2);

    if (tid == 0) { sm.a.mrun = -INFINITY; sm.a.srun = 0.f; }

    float cx0 = 0.f, cx1 = 0.f;
    const int d0 = tid * 2;

    const __half* hb = g_hh + (size_t)(b*ET_ + half*512)*U_;

    // prefetch tile 0
    const int pk  = tid >> 3;            // key within tile
    const int seg = tid & 7;             // 8 float4 segments per thread
    float4 r[8];
    {
        const float4* gp = (const float4*)(hb + (size_t)pk*U_) + seg;
#pragma unroll
        for (int i = 0; i < 8; ++i) r[i] = gp[i*8];
    }

    for (int tt = 0; tt < 16; ++tt) {
        __syncthreads();                         // prev ctx reads done (+init vis)
        // store tile into smem
        {
            float4* kr = (float4*)((char*)&sm.a.Kt[0][0] + (size_t)pk*520*2) + seg;
#pragma unroll
            for (int i = 0; i < 8; ++i) kr[i*8] = r[i];
        }
        // prefetch next tile
        if (tt < 15) {
            const float4* gp = (const float4*)(hb + (size_t)((tt+1)*32 + pk)*U_) + seg;
#pragma unroll
            for (int i = 0; i < 8; ++i) r[i] = gp[i*8];
        }
        __syncthreads();                         // tile ready

        // dots: warp w -> keys w*4 .. w*4+3
#pragma unroll
        for (int kk = 0; kk < 4; ++kk) {
            int key = w*4 + kk;
            const __half* kr = &sm.a.Kt[key][0];
            float d = 0.f;
#pragma unroll
            for (int j = 0; j < 8; ++j) {
                float2 kv = __half22float2(*(const __half2*)(kr + j*64 + lane*2));
                d += q2[j].x*kv.x + q2[j].y*kv.y;
            }
#pragma unroll
            for (int o = 16; o; o >>= 1) d += __shfl_xor_sync(0xffffffffu, d, o);
            if (lane == 0) sm.a.sc[key] = d;
        }
        __syncthreads();

        // warp0: tile softmax bookkeeping
        if (w == 0) {
            float s  = sm.a.sc[lane];
            float mx = s;
#pragma unroll
            for (int o = 16; o; o >>= 1) mx = fmaxf(mx, __shfl_xor_sync(0xffffffffu, mx, o));
            float mold = sm.a.mrun;
            float mnew = fmaxf(mold, mx);
            float p    = __expf(s - mnew);
            float ps   = p;
#pragma unroll
            for (int o = 16; o; o >>= 1) ps += __shfl_xor_sync(0xffffffffu, ps, o);
            sm.a.pp[lane] = p;
            if (lane == 0) {
                float corr = __expf(mold - mnew);
                sm.a.srun = sm.a.srun * corr + ps;
                sm.a.mrun = mnew;
                sm.a.corr = corr;
            }
        }
        __syncthreads();

        // ctx update: thread owns dims d0, d0+1
        {
            float corr = sm.a.corr;
            cx0 *= corr; cx1 *= corr;
#pragma unroll 8
            for (int kk = 0; kk < 32; ++kk) {
                float p = sm.a.pp[kk];
                float2 kv = __half22float2(*(const __half2*)(&sm.a.Kt[kk][0] + d0));
                cx0 += p * kv.x;
                cx1 += p * kv.y;
            }
        }
    }
    __syncthreads();

    // write partials
    if (tid == 0) { g_pm[cta] = sm.a.mrun; g_ps[cta] = sm.a.srun; }
    *(float2*)&g_pctx[cta][d0] = make_float2(cx0, cx1);
    __syncthreads();                  // ALL partial writes complete before publish
    __threadfence();
    if (tid == 0) *s_ticket = (int)atomicAdd(&g_aflag[b], 1u);
    __syncthreads();

    if ((*s_ticket) & 1) {            // second arriver merges
        __threadfence();
        int partner = cta ^ 1;
        float mO = sm.a.mrun, sO = sm.a.srun;
        float mP = __ldcg(&g_pm[partner]);
        float sP = __ldcg(&g_ps[partner]);
        float M  = fmaxf(mO, mP);
        float eO = __expf(mO - M);
        float eP = __expf(mP - M);
        float inv = __fdividef(1.f, sO*eO + sP*eP);
        float2 pcP;
        pcP.x = __ldcg(&g_pctx[partner][d0]);
        pcP.y = __ldcg(&g_pctx[partner][d0+1]);
        float c0 = (cx0*eO + pcP.x*eP) * inv;
        float c1 = (cx1*eO + pcP.y*eP) * inv;
        *(float2*)&g_ctx[b*U_ + d0] = make_float2(c0, c1);
        g_ctxT[(d0  )*B_ + b] = c0;
        g_ctxT[(d0+1)*B_ + b] = c1;
    }
    __syncthreads();
}

// ------------------------------- decoder -----------------------------------
// CTA pair per b: each computes 23 logits; second arriver does softmax+store.
__device__ __forceinline__ void decoder_phase(const float* __restrict__ h2o,
                                              const float* __restrict__ bd, int t,
                                              float* __restrict__ out, SmemU& sm,
                                              __shared__ int* s_ticket)
{
    const int cta  = blockIdx.x;
    const int tid  = threadIdx.x;
    const int lane = tid & 31;
    const int w    = tid >> 5;
    const int b    = cta >> 1;
    const int half = cta & 1;

#pragma unroll
    for (int i = 0; i < 4; ++i) {
        int k = tid + i*256;
        sm.d.st[k] = (k < 512) ? h2o[b*U_ + k] : g_ctx[b*U_ + k - 512];
    }
    __syncthreads();

    const float4* s4 = (const float4*)sm.d.st;
#pragma unroll
    for (int vv = 0; vv < 3; ++vv) {
        int vi = w*3 + vv;
        if (vi < 23) {
            int v = half*23 + vi;
            const float4* wr = (const float4*)(g_WdT + (size_t)v*1024);
            float a = 0.f;
#pragma unroll
            for (int kk = 0; kk < 8; ++kk) {
                float4 wv = wr[lane + kk*32];
                float4 sv = s4[lane + kk*32];
                a += wv.x*sv.x + wv.y*sv.y + wv.z*sv.z + wv.w*sv.w;
            }
#pragma unroll
            for (int o = 16; o; o >>= 1) a += __shfl_xor_sync(0xffffffffu, a, o);
            if (lane == 0) g_logits[b*48 + v] = a + bd[v];
        }
    }
    __syncthreads();                  // all logit writes complete before publish
    __threadfence();
    if (tid == 0) *s_ticket = (int)atomicAdd(&g_dflag[b], 1u);
    __syncthreads();

    if (((*s_ticket) & 1) && w == 0) {
        __threadfence();
        float x0 = (lane      < V_) ? __ldcg(&g_logits[b*48 + lane])      : -INFINITY;
        float x1 = (lane + 32 < V_) ? __ldcg(&g_logits[b*48 + lane + 32]) : -INFINITY;
        float mx = fmaxf(x0, x1);
#pragma unroll
        for (int o = 16; o; o >>= 1) mx = fmaxf(mx, __shfl_xor_sync(0xffffffffu, mx, o));
        float e0 = (lane      < V_) ? __expf(x0 - mx) : 0.f;
        float e1 = (lane + 32 < V_) ? __expf(x1 - mx) : 0.f;
        float ss = e0 + e1;
#pragma unroll
        for (int o = 16; o; o >>= 1) ss += __shfl_xor_sync(0xffffffffu, ss, o);
        float inv = __fdividef(1.f, ss);
        float* op = out + ((size_t)b*T_ + t)*V_;
        if (lane      < V_) op[lane]      = e0*inv;
        if (lane + 32 < V_) op[lane + 32] = e1*inv;
    }
    __syncthreads();
}

// --------------------------- persistent kernel -----------------------------
__global__ void __launch_bounds__(NTHR)
speller_persistent(const float* __restrict__ h,  const float* __restrict__ y,
                   const float* __restrict__ W1, const float* __restrict__ U1,
                   const float* __restrict__ b1, const float* __restrict__ W2,
                   const float* __restrict__ U2, const float* __restrict__ b2,
                   const float* __restrict__ Wd, const float* __restrict__ bd,
                   float* __restrict__ out)
{
    __shared__ SmemU sm;
    __shared__ int s_ticket;
    const int gtid = blockIdx.x*NTHR + threadIdx.x;     // 0..32767

    // ---- prologue ----
    g_h1[0][gtid]=0.f; g_h1[1][gtid]=0.f; g_c1[0][gtid]=0.f; g_c1[1][gtid]=0.f;
    g_h2[0][gtid]=0.f; g_h2[1][gtid]=0.f; g_c2[0][gtid]=0.f; g_c2[1][gtid]=0.f;
    g_h1T[0][gtid]=0.f; g_h1T[1][gtid]=0.f; g_h2T[0][gtid]=0.f; g_h2T[1][gtid]=0.f;
    g_ctx[gtid]=0.f; g_ctxT[gtid]=0.f;

    for (int idx = gtid; idx < NCTA*1024*16; idx += NCTA*NTHR) {
        int c = idx >> 14;
        int r = idx & 16383;
        int k = r >> 4;
        int j = r & 15;
        int gate = j >> 2, uu = j & 3;
        int col = gate*512 + c*4 + uu;
        g_Wt1[idx] = (k < 512) ? (W1[(size_t)k*NG_ + col] + U1[(size_t)k*NG_ + col])
                               : W1[(size_t)(k+1)*NG_ + col];
        g_Wt2[idx] = (k < 512) ? W2[(size_t)k*NG_ + col]
                               : U2[(size_t)(k-512)*NG_ + col];
    }
    if (gtid < NG_) g_w1y[gtid] = W1[(size_t)512*NG_ + gtid];
    for (int idx = gtid; idx < V_*1024; idx += NCTA*NTHR)
        g_WdT[idx] = Wd[(size_t)(idx & 1023)*V_ + (idx >> 10)];
    {
        const float2* h2p = (const float2*)h;
        __half2* hhp = (__half2*)g_hh;
        const size_t n2 = (size_t)B_*ET_*U_/2;
        for (size_t i = gtid; i < n2; i += NCTA*NTHR)
            hhp[i] = __float22half2_rn(h2p[i]);
    }
    grid_barrier();

    // ---- 256 decode steps ----
    for (int t = 0; t < T_; ++t) {
        const int in = t & 1, outb = in ^ 1;

        gemm_gate_phase(0, g_h1T[in], g_ctxT, g_Wt1, b1,
                        g_c1[in], g_h1[outb], g_c1[outb], g_h1T[outb], y, t, sm);
        grid_barrier();

        attn_phase(g_h1[outb], sm, &s_ticket);
        grid_barrier();

        gemm_gate_phase(1, g_ctxT, g_h2T[in], g_Wt2, b2,
                        g_c2[in], g_h2[outb], g_c2[outb], g_h2T[outb], nullptr, t, sm);
        grid_barrier();

        decoder_phase(g_h2[outb], bd, t, out, sm, &s_ticket);
        // no barrier: next gemm1 writes only h1/c1 buffers the decoder never reads
    }
}

// ------------------------------- launcher ----------------------------------
extern "C" void kernel_launch(void* const* d_in, const int* in_sizes, int n_in,
                              void* d_out, int out_size)
{
    (void)in_sizes; (void)n_in; (void)out_size;
    const float* h  = (const float*)d_in[0];
    const float* y  = (const float*)d_in[1];
    const float* W1 = (const float*)d_in[2];
    const float* U1 = (const float*)d_in[3];
    const float* b1 = (const float*)d_in[4];
    const float* W2 = (const float*)d_in[5];
    const float* U2 = (const float*)d_in[6];
    const float* b2 = (const float*)d_in[7];
    const float* Wd = (const float*)d_in[8];
    const float* bd = (const float*)d_in[9];
    float* out = (float*)d_out;

    speller_persistent<<<NCTA, NTHR>>>(h, y, W1, U1, b1, W2, U2, b2, Wd, bd, out);
}

// round 6
// speedup vs baseline: 1.7998x; 1.2372x over previous
#include <cuda_runtime.h>
#include <cuda_fp16.h>
#include <math.h>

#define B_   64
#define T_   256
#define ET_  1024
#define U_   512
#define V_   46
#define NG_  2048
#define NCTA 128
#define NTHR 256

// ------------------------- persistent device state -------------------------
__device__ float g_h1[B_*U_];
__device__ float g_c1[B_*U_];
__device__ float g_h2[B_*U_];
__device__ float g_c2[B_*U_];
__device__ float g_ctx[B_*U_];

__device__ __half g_hh[(size_t)B_*ET_*U_];          // 67 MB fp16 copy of h

// per-CTA mma weight slices: [layer][cta][n_local 128][k_local 128], tf32-rounded
__device__ float g_WtA[(size_t)2*NCTA*128*128];
__device__ float g_w1y[NG_];
__device__ float g_WdT[V_*1024];

__device__ float g_Zp[2][8][B_][NG_];               // partials per layer/ksplit
__device__ float g_sc[B_*ET_];                      // raw attention scores
__device__ float g_pctx[NCTA][U_];                  // partial ctx
__device__ float g_logits[B_*48];

__device__ unsigned int g_fG1[B_];                  // gate1 halves done
__device__ unsigned int g_fS[B_];                   // score halves done
__device__ unsigned int g_fC[B_];                   // ctx merge ticket
__device__ unsigned int g_fH2[B_];                  // gate2 halves done
__device__ unsigned int g_fL[B_];                   // logits merge ticket
__device__ unsigned int g_bar_count = 0;
__device__ unsigned int g_bar_gen   = 0;

// smem layout (floats): [0, 33792) persistent weights (2 x 128 x 132)
//                       [33792, 42240) scratch union (A-tile / attn / decoder)
#define WSM_FLOATS   (2*128*132)
#define SCR_FLOATS   (64*132)
#define SMEM_BYTES   ((WSM_FLOATS + SCR_FLOATS) * 4)

// ------------------------------ small helpers ------------------------------
__device__ __forceinline__ float tf32r(float x) {
    unsigned int r;
    asm("cvt.rna.tf32.f32 %0, %1;" : "=r"(r) : "f"(x));
    return __uint_as_float(r);
}
__device__ __forceinline__ void mma_tf32(float& c0, float& c1, float& c2, float& c3,
                                         float a0, float a1, float a2, float a3,
                                         float b0, float b1) {
    asm("mma.sync.aligned.m16n8k8.row.col.f32.tf32.tf32.f32 "
        "{%0,%1,%2,%3}, {%4,%5,%6,%7}, {%8,%9}, {%0,%1,%2,%3};"
        : "+f"(c0), "+f"(c1), "+f"(c2), "+f"(c3)
        : "r"(__float_as_uint(a0)), "r"(__float_as_uint(a1)),
          "r"(__float_as_uint(a2)), "r"(__float_as_uint(a3)),
          "r"(__float_as_uint(b0)), "r"(__float_as_uint(b1)));
}
__device__ __forceinline__ float fsig(float x)  { return __fdividef(1.f, 1.f + __expf(-x)); }
__device__ __forceinline__ float ftanh(float x) { return __fdividef(2.f, 1.f + __expf(-2.f*x)) - 1.f; }

// ------------------------------ grid barrier -------------------------------
__device__ __forceinline__ void grid_barrier()
{
    __syncthreads();
    if (threadIdx.x == 0) {
        unsigned int gen = *(volatile unsigned int*)&g_bar_gen;
        __threadfence();
        unsigned int ticket = atomicAdd(&g_bar_count, 1u);
        if (ticket == gridDim.x - 1) {
            atomicExch(&g_bar_count, 0u);
            __threadfence();
            *(volatile unsigned int*)&g_bar_gen = gen + 1u;
        } else {
            while (*(volatile unsigned int*)&g_bar_gen == gen) { __nanosleep(64); }
        }
        __threadfence();
    }
    __syncthreads();
}

// publish: all threads wrote globals -> bump counter
__device__ __forceinline__ void flag_bump(unsigned int* f)
{
    __syncthreads();
    __threadfence();
    if (threadIdx.x == 0) atomicAdd(f, 1u);
    __syncthreads();
}
// wait until counter reaches target (monotonic within launch)
__device__ __forceinline__ void flag_wait(unsigned int* f, unsigned int target)
{
    if (threadIdx.x == 0) {
        while (*(volatile unsigned int*)f < target) { __nanosleep(32); }
        __threadfence();
    }
    __syncthreads();
}

// ----------------------------- tensor-core GEMM ----------------------------
// CTA = (nt = cta&15, ks = cta>>4). Computes partial z[layer] for
// cols nt*128..+127, k-range ks*128..+127 over all 64 batch rows.
__device__ __forceinline__ void mma_phase(int layer, float* smemf)
{
    const int cta = blockIdx.x;
    const int tid = threadIdx.x;
    const int nt = cta & 15, ks = cta >> 4;
    const int kg0 = ks * 128;

    const float* __restrict__ SA = layer ? g_ctx : g_h1;
    const float* __restrict__ SB = layer ? g_h2  : g_ctx;
    const float* __restrict__ S  = (kg0 < 512) ? (SA + kg0) : (SB + (kg0 - 512));

    float* Asm = smemf + WSM_FLOATS;                 // [64][132]
    const float* Wl = smemf + layer * (128*132);     // [128 n][132 k]

    // stage A slice: row r (=b), cols qd*32..+31
    {
        const int r  = tid >> 2;
        const int qd = tid & 3;
        const float* src = S + (size_t)r * U_ + qd * 32;
        float* dst = Asm + r * 132 + qd * 32;
#pragma unroll
        for (int j = 0; j < 8; ++j) {
            float4 v = *(const float4*)(src + j * 4);
            dst[j*4 + 0] = tf32r(v.x);
            dst[j*4 + 1] = tf32r(v.y);
            dst[j*4 + 2] = tf32r(v.z);
            dst[j*4 + 3] = tf32r(v.w);
        }
    }
    __syncthreads();

    const int w    = tid >> 5;
    const int lane = tid & 31;
    const int g    = lane >> 2;
    const int l4   = lane & 3;
    const int mt   = w >> 1;             // 0..3
    const int nh   = w & 1;              // 0..1
    const int m0   = mt * 16;

    float c[8][4];
#pragma unroll
    for (int ti = 0; ti < 8; ++ti)
#pragma unroll
        for (int q = 0; q < 4; ++q) c[ti][q] = 0.f;

    const float* Ar0 = Asm + (m0 + g) * 132;
    const float* Ar1 = Ar0 + 8 * 132;

#pragma unroll
    for (int kt = 0; kt < 16; ++kt) {
        const int kq = kt * 8 + l4;
        float a0 = Ar0[kq];
        float a1 = Ar1[kq];
        float a2 = Ar0[kq + 4];
        float a3 = Ar1[kq + 4];
#pragma unroll
        for (int ti = 0; ti < 8; ++ti) {
            const float* Wn = Wl + (nh*64 + ti*8 + g) * 132;
            float b0 = Wn[kq];
            float b1 = Wn[kq + 4];
            mma_tf32(c[ti][0], c[ti][1], c[ti][2], c[ti][3], a0, a1, a2, a3, b0, b1);
        }
    }

    // write partials
    float* zp = &g_Zp[layer][ks][0][0];
#pragma unroll
    for (int ti = 0; ti < 8; ++ti) {
        int nb = nt*128 + nh*64 + ti*8 + 2*l4;
        int r0 = m0 + g;
        *(float2*)(zp + (size_t)r0*NG_ + nb)     = make_float2(c[ti][0], c[ti][1]);
        *(float2*)(zp + (size_t)(r0+8)*NG_ + nb) = make_float2(c[ti][2], c[ti][3]);
    }
    __syncthreads();
}

// ---------------- LSTM gate for one (b, u-half): 256 u's ------------------
__device__ __forceinline__ void gate_half(int layer, int b, int uh,
                                          const float* __restrict__ bias,
                                          const float* __restrict__ y, int t,
                                          float* __restrict__ cS, float* __restrict__ hS)
{
    const int u = uh*256 + threadIdx.x;
    float z0=0.f, z1=0.f, z2=0.f, z3=0.f;
#pragma unroll
    for (int p = 0; p < 8; ++p) {
        const float* zb = &g_Zp[layer][p][b][0];
        z0 += zb[u]; z1 += zb[512+u]; z2 += zb[1024+u]; z3 += zb[1536+u];
    }
    z0 += bias[u]; z1 += bias[512+u]; z2 += bias[1024+u]; z3 += bias[1536+u];
    if (layer == 0) {
        float yv = y[b*T_ + t];
        z0 += yv*g_w1y[u]; z1 += yv*g_w1y[512+u];
        z2 += yv*g_w1y[1024+u]; z3 += yv*g_w1y[1536+u];
    }
    float si = fsig(z0), sf = fsig(z1), tg = ftanh(z2), so = fsig(z3);
    float cn = sf * cS[b*U_ + u] + si * tg;
    cS[b*U_ + u] = cn;
    hS[b*U_ + u] = so * ftanh(cn);
}

// ------------------------- attention (two-pass) ----------------------------
__device__ __forceinline__ void attn_phase(const float* __restrict__ b1v,
                                           const float* __restrict__ y, int t,
                                           float* smemf)
{
    const int cta  = blockIdx.x;
    const int tid  = threadIdx.x;
    const int lane = tid & 31;
    const int w    = tid >> 5;
    const int b    = cta >> 1;
    const int uh   = cta & 1;
    const unsigned int tgt = 2u*(t+1);

    float* sc  = smemf + WSM_FLOATS;        // [512] own-half scores
    float* psm = sc + 512;                  // [512] normalized probs
    float* red = psm + 512;                 // [256] reduction scratch

    // ---- gate1 for this (b, half) ----
    gate_half(0, b, uh, b1v, y, t, g_c1, g_h1);
    flag_bump(&g_fG1[b]);
    flag_wait(&g_fG1[b], tgt);

    // ---- q slice: 16 floats at lane*16 ----
    float qr[16];
    {
        const float* qp = g_h1 + b*U_ + lane*16;
#pragma unroll
        for (int j = 0; j < 4; ++j) {
            float4 v = __ldcg((const float4*)(qp + j*4));
            qr[j*4+0]=v.x; qr[j*4+1]=v.y; qr[j*4+2]=v.z; qr[j*4+3]=v.w;
        }
    }

    // ---- pass 1: scores for own 512 keys (warp w -> keys w*64..+63) ----
    const __half* hb = g_hh + ((size_t)(b*ET_ + uh*512))*U_;
#pragma unroll 2
    for (int i = 0; i < 64; ++i) {
        const int kloc = w*64 + i;
        const int4* hp = (const int4*)(hb + (size_t)kloc*U_ + lane*16);
        int4 v0 = __ldcg(hp);
        int4 v1 = __ldcg(hp + 1);
        float d = 0.f;
        const __half2* h0 = (const __half2*)&v0;
        const __half2* h1p = (const __half2*)&v1;
#pragma unroll
        for (int j = 0; j < 4; ++j) {
            float2 f0 = __half22float2(h0[j]);
            float2 f1 = __half22float2(h1p[j]);
            d += qr[2*j]*f0.x + qr[2*j+1]*f0.y;
            d += qr[8+2*j]*f1.x + qr[8+2*j+1]*f1.y;
        }
#pragma unroll
        for (int o = 16; o; o >>= 1) d += __shfl_xor_sync(0xffffffffu, d, o);
        if (lane == 0) {
            sc[kloc] = d;
            g_sc[b*ET_ + uh*512 + kloc] = d;
        }
    }
    flag_bump(&g_fS[b]);
    flag_wait(&g_fS[b], tgt);

    // ---- redundant deterministic max/sum over all 1024 scores ----
    float s0 = __ldcg(&g_sc[b*ET_ + tid]);
    float s1 = __ldcg(&g_sc[b*ET_ + tid + 256]);
    float s2 = __ldcg(&g_sc[b*ET_ + tid + 512]);
    float s3 = __ldcg(&g_sc[b*ET_ + tid + 768]);
    red[tid] = fmaxf(fmaxf(s0, s1), fmaxf(s2, s3));
    __syncthreads();
#pragma unroll
    for (int s = 128; s; s >>= 1) {
        if (tid < s) red[tid] = fmaxf(red[tid], red[tid + s]);
        __syncthreads();
    }
    const float M = red[0];
    __syncthreads();
    red[tid] = __expf(s0 - M) + __expf(s1 - M) + __expf(s2 - M) + __expf(s3 - M);
    __syncthreads();
#pragma unroll
    for (int s = 128; s; s >>= 1) {
        if (tid < s) red[tid] = red[tid] + red[tid + s];
        __syncthreads();
    }
    const float invS = __fdividef(1.f, red[0]);
    __syncthreads();

    // normalized probs for own half
    psm[tid]       = __expf(sc[tid]       - M) * invS;
    psm[tid + 256] = __expf(sc[tid + 256] - M) * invS;
    __syncthreads();

    // ---- pass 2: partial ctx over own 512 keys; thread owns dims d0,d0+1 ----
    const int d0 = tid * 2;
    float cx0 = 0.f, cx1 = 0.f;
    const __half* hd = hb + d0;
#pragma unroll 4
    for (int k = 0; k < 512; ++k) {
        float p = psm[k];
        float2 f = __half22float2(*(const __half2*)(hd + (size_t)k*U_));
        cx0 += p * f.x;
        cx1 += p * f.y;
    }
    *(float2*)&g_pctx[cta][d0] = make_float2(cx0, cx1);

    // ---- pair merge (second arriver) ----
    __shared__ int s_ticket;
    __syncthreads();
    __threadfence();
    if (tid == 0) s_ticket = (int)atomicAdd(&g_fC[b], 1u);
    __syncthreads();
    if (s_ticket & 1) {
        __threadfence();
        const int partner = cta ^ 1;
        float2 pp;
        pp.x = __ldcg(&g_pctx[partner][d0]);
        pp.y = __ldcg(&g_pctx[partner][d0+1]);
        *(float2*)&g_ctx[b*U_ + d0] = make_float2(cx0 + pp.x, cx1 + pp.y);
    }
    __syncthreads();
}

// ------------------------------- decoder -----------------------------------
__device__ __forceinline__ void decoder_phase(const float* __restrict__ b2v,
                                              const float* __restrict__ bd, int t,
                                              float* __restrict__ out, float* smemf)
{
    const int cta  = blockIdx.x;
    const int tid  = threadIdx.x;
    const int lane = tid & 31;
    const int w    = tid >> 5;
    const int b    = cta >> 1;
    const int uh   = cta & 1;
    const unsigned int tgt = 2u*(t+1);

    float* st = smemf + WSM_FLOATS;         // [1024]

    // gate2 for this (b, half)
    gate_half(1, b, uh, b2v, nullptr, t, g_c2, g_h2);
    flag_bump(&g_fH2[b]);
    flag_wait(&g_fH2[b], tgt);

#pragma unroll
    for (int i = 0; i < 4; ++i) {
        int k = tid + i*256;
        st[k] = (k < 512) ? __ldcg(&g_h2[b*U_ + k]) : g_ctx[b*U_ + k - 512];
    }
    __syncthreads();

    const float4* s4 = (const float4*)st;
#pragma unroll
    for (int vv = 0; vv < 3; ++vv) {
        int vi = w*3 + vv;
        if (vi < 23) {
            int v = uh*23 + vi;
            const float4* wr = (const float4*)(g_WdT + (size_t)v*1024);
            float a = 0.f;
#pragma unroll
            for (int kk = 0; kk < 8; ++kk) {
                float4 wv = wr[lane + kk*32];
                float4 sv = s4[lane + kk*32];
                a += wv.x*sv.x + wv.y*sv.y + wv.z*sv.z + wv.w*sv.w;
            }
#pragma unroll
            for (int o = 16; o; o >>= 1) a += __shfl_xor_sync(0xffffffffu, a, o);
            if (lane == 0) g_logits[b*48 + v] = a + bd[v];
        }
    }

    __shared__ int s_ticket;
    __syncthreads();
    __threadfence();
    if (tid == 0) s_ticket = (int)atomicAdd(&g_fL[b], 1u);
    __syncthreads();

    if ((s_ticket & 1) && w == 0) {
        __threadfence();
        float x0 = (lane      < V_) ? __ldcg(&g_logits[b*48 + lane])      : -INFINITY;
        float x1 = (lane + 32 < V_) ? __ldcg(&g_logits[b*48 + lane + 32]) : -INFINITY;
        float mx = fmaxf(x0, x1);
#pragma unroll
        for (int o = 16; o; o >>= 1) mx = fmaxf(mx, __shfl_xor_sync(0xffffffffu, mx, o));
        float e0 = (lane      < V_) ? __expf(x0 - mx) : 0.f;
        float e1 = (lane + 32 < V_) ? __expf(x1 - mx) : 0.f;
        float ss = e0 + e1;
#pragma unroll
        for (int o = 16; o; o >>= 1) ss += __shfl_xor_sync(0xffffffffu, ss, o);
        float inv = __fdividef(1.f, ss);
        float* op = out + ((size_t)b*T_ + t)*V_;
        if (lane      < V_) op[lane]      = e0*inv;
        if (lane + 32 < V_) op[lane + 32] = e1*inv;
    }
    __syncthreads();
}

// --------------------------- persistent kernel -----------------------------
__global__ void __launch_bounds__(NTHR)
speller_persistent(const float* __restrict__ h,  const float* __restrict__ y,
                   const float* __restrict__ W1, const float* __restrict__ U1,
                   const float* __restrict__ b1, const float* __restrict__ W2,
                   const float* __restrict__ U2, const float* __restrict__ b2,
                   const float* __restrict__ Wd, const float* __restrict__ bd,
                   float* __restrict__ out)
{
    extern __shared__ float smemf[];
    const int tid  = threadIdx.x;
    const int cta  = blockIdx.x;
    const int gtid = cta*NTHR + tid;              // 0..32767

    // ---- prologue ----
    g_h1[gtid]=0.f; g_c1[gtid]=0.f; g_h2[gtid]=0.f; g_c2[gtid]=0.f; g_ctx[gtid]=0.f;
    if (gtid < B_) {
        g_fG1[gtid]=0u; g_fS[gtid]=0u; g_fC[gtid]=0u; g_fH2[gtid]=0u; g_fL[gtid]=0u;
    }

    // weight fold into per-CTA mma slices (tf32-rounded)
    for (size_t idx = gtid; idx < (size_t)2*NCTA*128*128; idx += (size_t)NCTA*NTHR) {
        int layer = (int)(idx >> 21);
        int rem   = (int)(idx & ((1u<<21) - 1));
        int c  = rem >> 14;
        int r2 = rem & 16383;
        int nl = r2 >> 7;
        int kl = r2 & 127;
        int nt = c & 15, ks = c >> 4;
        int n  = nt*128 + nl;
        int kg = ks*128 + kl;
        float v;
        if (layer == 0)
            v = (kg < 512) ? (W1[(size_t)kg*NG_ + n] + U1[(size_t)kg*NG_ + n])
                           : W1[(size_t)(kg+1)*NG_ + n];
        else
            v = (kg < 512) ? W2[(size_t)kg*NG_ + n]
                           : U2[(size_t)(kg-512)*NG_ + n];
        g_WtA[idx] = tf32r(v);
    }
    if (gtid < NG_) g_w1y[gtid] = W1[(size_t)512*NG_ + gtid];
    for (int idx = gtid; idx < V_*1024; idx += NCTA*NTHR)
        g_WdT[idx] = Wd[(size_t)(idx & 1023)*V_ + (idx >> 10)];
    {
        const float2* h2p = (const float2*)h;
        __half2* hhp = (__half2*)g_hh;
        const size_t n2 = (size_t)B_*ET_*U_/2;
        for (size_t i = gtid; i < n2; i += (size_t)NCTA*NTHR)
            hhp[i] = __float22half2_rn(h2p[i]);
    }
    grid_barrier();

    // copy this CTA's weight slices to persistent smem (pad 128->132)
    for (int i = tid; i < 2*128*128; i += NTHR) {
        int layer = i >> 14;
        int nl = (i >> 7) & 127;
        int kl = i & 127;
        smemf[layer*(128*132) + nl*132 + kl] =
            g_WtA[((size_t)layer*NCTA + cta)*16384 + nl*128 + kl];
    }
    __syncthreads();

    // ---- 256 decode steps ----
    for (int t = 0; t < T_; ++t) {
        mma_phase(0, smemf);
        grid_barrier();
        attn_phase(b1, y, t, smemf);
        grid_barrier();
        mma_phase(1, smemf);
        grid_barrier();
        decoder_phase(b2, bd, t, out, smemf);
        // no barrier: next mma1 writes g_Zp[0]; decoder reads g_Zp[1], and the
        // post-mma1 barrier orders decoder(t) before attn(t+1)'s partial reads.
    }
}

// ------------------------------- launcher ----------------------------------
extern "C" void kernel_launch(void* const* d_in, const int* in_sizes, int n_in,
                              void* d_out, int out_size)
{
    (void)in_sizes; (void)n_in; (void)out_size;
    const float* h  = (const float*)d_in[0];
    const float* y  = (const float*)d_in[1];
    const float* W1 = (const float*)d_in[2];
    const float* U1 = (const float*)d_in[3];
    const float* b1 = (const float*)d_in[4];
    const float* W2 = (const float*)d_in[5];
    const float* U2 = (const float*)d_in[6];
    const float* b2 = (const float*)d_in[7];
    const float* Wd = (const float*)d_in[8];
    const float* bd = (const float*)d_in[9];
    float* out = (float*)d_out;

    cudaFuncSetAttribute(speller_persistent,
                         cudaFuncAttributeMaxDynamicSharedMemorySize, SMEM_BYTES);
    speller_persistent<<<NCTA, NTHR, SMEM_BYTES>>>(h, y, W1, U1, b1, W2, U2, b2,
                                                   Wd, bd, out);
}

// round 9
// speedup vs baseline: 2.2519x; 1.2512x over previous
#include <cuda_runtime.h>
#include <cuda_fp16.h>
#include <math.h>

#define B_   64
#define T_   256
#define ET_  1024
#define U_   512
#define V_   46
#define NG_  2048
#define NCTA 128
#define NTHR 256

// ------------------------- persistent device state -------------------------
__device__ float g_h1[B_*U_];
__device__ float g_c1[B_*U_];
__device__ float g_h2[B_*U_];
__device__ float g_c2[B_*U_];
__device__ float g_ctx[B_*U_];

__device__ __half g_hh[(size_t)B_*ET_*U_];          // 67 MB fp16 copy of h

// per-CTA mma weight slices: [layer][cta][n_local 128][k_local 128], tf32-rounded
__device__ float g_WtA[(size_t)2*NCTA*128*128];
__device__ float g_w1y[NG_];
__device__ float g_WdT[V_*1024];

__device__ float g_Zp[2][8][B_][NG_];               // partials per layer/ksplit
__device__ float g_sc[B_*ET_];                      // raw attention scores
__device__ float g_pctx[NCTA][U_];                  // partial ctx
__device__ float g_logits[B_*48];

__device__ unsigned int g_fG1[B_];                  // gate1 halves done
__device__ unsigned int g_fS[B_];                   // score halves done
__device__ unsigned int g_fC[B_];                   // ctx merge ticket
__device__ unsigned int g_fH2[B_];                  // gate2 halves done
__device__ unsigned int g_fL[B_];                   // logits merge ticket
__device__ unsigned int g_bar_count = 0;
__device__ unsigned int g_bar_gen   = 0;

// smem layout (floats): [0, 33792) persistent weights (2 x 128 x 132)
//   scratch base (WSM_FLOATS):
//     mma:      Asm 64x132 = 8448
//     attn:     sc[512] psm[512] red[256]  then TILE at +1280: 8448 (32x528 half)
//     decoder:  st[1024]
#define WSM_FLOATS   (2*128*132)
#define TILE_OFF     (WSM_FLOATS + 1280)
#define SMEM_FLOATS  (TILE_OFF + 8448)
#define SMEM_BYTES   (SMEM_FLOATS * 4)

// ------------------------------ small helpers ------------------------------
__device__ __forceinline__ float tf32r(float x) {
    unsigned int r;
    asm("cvt.rna.tf32.f32 %0, %1;" : "=r"(r) : "f"(x));
    return __uint_as_float(r);
}
__device__ __forceinline__ void mma_tf32(float& c0, float& c1, float& c2, float& c3,
                                         float a0, float a1, float a2, float a3,
                                         float b0, float b1) {
    asm("mma.sync.aligned.m16n8k8.row.col.f32.tf32.tf32.f32 "
        "{%0,%1,%2,%3}, {%4,%5,%6,%7}, {%8,%9}, {%0,%1,%2,%3};"
        : "+f"(c0), "+f"(c1), "+f"(c2), "+f"(c3)
        : "r"(__float_as_uint(a0)), "r"(__float_as_uint(a1)),
          "r"(__float_as_uint(a2)), "r"(__float_as_uint(a3)),
          "r"(__float_as_uint(b0)), "r"(__float_as_uint(b1)));
}
__device__ __forceinline__ float fsig(float x)  { return __fdividef(1.f, 1.f + __expf(-x)); }
__device__ __forceinline__ float ftanh(float x) { return __fdividef(2.f, 1.f + __expf(-2.f*x)) - 1.f; }

// ------------------------------ grid barrier -------------------------------
__device__ __forceinline__ void grid_barrier()
{
    __syncthreads();
    if (threadIdx.x == 0) {
        unsigned int gen = *(volatile unsigned int*)&g_bar_gen;
        __threadfence();
        unsigned int ticket = atomicAdd(&g_bar_count, 1u);
        if (ticket == gridDim.x - 1) {
            atomicExch(&g_bar_count, 0u);
            __threadfence();
            *(volatile unsigned int*)&g_bar_gen = gen + 1u;
        } else {
            while (*(volatile unsigned int*)&g_bar_gen == gen) { __nanosleep(64); }
        }
        __threadfence();
    }
    __syncthreads();
}

__device__ __forceinline__ void flag_bump(unsigned int* f)
{
    __syncthreads();
    __threadfence();
    if (threadIdx.x == 0) atomicAdd(f, 1u);
    __syncthreads();
}
__device__ __forceinline__ void flag_wait(unsigned int* f, unsigned int target)
{
    if (threadIdx.x == 0) {
        while (*(volatile unsigned int*)f < target) { __nanosleep(32); }
        __threadfence();
    }
    __syncthreads();
}

// ----------------------------- tensor-core GEMM ----------------------------
// CTA = (nt = cta&15, ks = cta>>4). Computes partial z[layer] for
// cols nt*128..+127, k-range ks*128..+127 over all 64 batch rows.
__device__ __forceinline__ void mma_phase(int layer, float* smemf)
{
    const int cta = blockIdx.x;
    const int tid = threadIdx.x;
    const int nt = cta & 15, ks = cta >> 4;
    const int kg0 = ks * 128;

    const float* __restrict__ SA = layer ? g_ctx : g_h1;
    const float* __restrict__ SB = layer ? g_h2  : g_ctx;
    const float* __restrict__ S  = (kg0 < 512) ? (SA + kg0) : (SB + (kg0 - 512));

    float* Asm = smemf + WSM_FLOATS;                 // [64][132]
    const float* Wl = smemf + layer * (128*132);     // [128 n][132 k]

    // stage A slice: row r (=b), cols qd*32..+31
    {
        const int r  = tid >> 2;
        const int qd = tid & 3;
        const float* src = S + (size_t)r * U_ + qd * 32;
        float* dst = Asm + r * 132 + qd * 32;
#pragma unroll
        for (int j = 0; j < 8; ++j) {
            float4 v = *(const float4*)(src + j * 4);
            dst[j*4 + 0] = tf32r(v.x);
            dst[j*4 + 1] = tf32r(v.y);
            dst[j*4 + 2] = tf32r(v.z);
            dst[j*4 + 3] = tf32r(v.w);
        }
    }
    __syncthreads();

    const int w    = tid >> 5;
    const int lane = tid & 31;
    const int g    = lane >> 2;
    const int l4   = lane & 3;
    const int mt   = w >> 1;             // 0..3
    const int nh   = w & 1;              // 0..1
    const int m0   = mt * 16;

    float c[8][4];
#pragma unroll
    for (int ti = 0; ti < 8; ++ti)
#pragma unroll
        for (int q = 0; q < 4; ++q) c[ti][q] = 0.f;

    const float* Ar0 = Asm + (m0 + g) * 132;
    const float* Ar1 = Ar0 + 8 * 132;

#pragma unroll
    for (int kt = 0; kt < 16; ++kt) {
        const int kq = kt * 8 + l4;
        float a0 = Ar0[kq];
        float a1 = Ar1[kq];
        float a2 = Ar0[kq + 4];
        float a3 = Ar1[kq + 4];
#pragma unroll
        for (int ti = 0; ti < 8; ++ti) {
            const float* Wn = Wl + (nh*64 + ti*8 + g) * 132;
            float b0 = Wn[kq];
            float b1 = Wn[kq + 4];
            mma_tf32(c[ti][0], c[ti][1], c[ti][2], c[ti][3], a0, a1, a2, a3, b0, b1);
        }
    }

    // write partials
    float* zp = &g_Zp[layer][ks][0][0];
#pragma unroll
    for (int ti = 0; ti < 8; ++ti) {
        int nb = nt*128 + nh*64 + ti*8 + 2*l4;
        int r0 = m0 + g;
        *(float2*)(zp + (size_t)r0*NG_ + nb)     = make_float2(c[ti][0], c[ti][1]);
        *(float2*)(zp + (size_t)(r0+8)*NG_ + nb) = make_float2(c[ti][2], c[ti][3]);
    }
    __syncthreads();
}

// ---------------- LSTM gate for one (b, u-half): 256 u's ------------------
__device__ __forceinline__ void gate_half(int layer, int b, int uh,
                                          const float* __restrict__ bias,
                                          const float* __restrict__ y, int t,
                                          float* __restrict__ cS, float* __restrict__ hS)
{
    const int u = uh*256 + threadIdx.x;
    float z0=0.f, z1=0.f, z2=0.f, z3=0.f;
#pragma unroll
    for (int p = 0; p < 8; ++p) {
        const float* zb = &g_Zp[layer][p][b][0];
        z0 += zb[u]; z1 += zb[512+u]; z2 += zb[1024+u]; z3 += zb[1536+u];
    }
    z0 += bias[u]; z1 += bias[512+u]; z2 += bias[1024+u]; z3 += bias[1536+u];
    if (layer == 0) {
        float yv = y[b*T_ + t];
        z0 += yv*g_w1y[u]; z1 += yv*g_w1y[512+u];
        z2 += yv*g_w1y[1024+u]; z3 += yv*g_w1y[1536+u];
    }
    float si = fsig(z0), sf = fsig(z1), tg = ftanh(z2), so = fsig(z3);
    float cn = sf * cS[b*U_ + u] + si * tg;
    cS[b*U_ + u] = cn;
    hS[b*U_ + u] = so * ftanh(cn);
}

// ------------------------- attention (two-pass) ----------------------------
__device__ __forceinline__ void attn_phase(const float* __restrict__ b1v,
                                           const float* __restrict__ y, int t,
                                           float* smemf)
{
    const int cta  = blockIdx.x;
    const int tid  = threadIdx.x;
    const int lane = tid & 31;
    const int w    = tid >> 5;
    const int b    = cta >> 1;
    const int uh   = cta & 1;
    const unsigned int tgt = 2u*(t+1);

    float* sc  = smemf + WSM_FLOATS;        // [512] own-half scores
    float* psm = sc + 512;                  // [512] normalized probs
    float* red = psm + 512;                 // [256] reduction scratch

    // ---- gate1 for this (b, half) ----
    gate_half(0, b, uh, b1v, y, t, g_c1, g_h1);
    flag_bump(&g_fG1[b]);
    flag_wait(&g_fG1[b], tgt);

    // ---- q slice: 16 floats at lane*16 ----
    float qr[16];
    {
        const float* qp = g_h1 + b*U_ + lane*16;
#pragma unroll
        for (int j = 0; j < 4; ++j) {
            float4 v = __ldcg((const float4*)(qp + j*4));
            qr[j*4+0]=v.x; qr[j*4+1]=v.y; qr[j*4+2]=v.z; qr[j*4+3]=v.w;
        }
    }

    // ---- pass 1: scores for own 512 keys (warp w -> keys w*64..+63) ----
    const __half* hb = g_hh + ((size_t)(b*ET_ + uh*512))*U_;
#pragma unroll 2
    for (int i = 0; i < 64; ++i) {
        const int kloc = w*64 + i;
        const int4* hp = (const int4*)(hb + (size_t)kloc*U_ + lane*16);
        int4 v0 = __ldcg(hp);
        int4 v1 = __ldcg(hp + 1);
        float d = 0.f;
        const __half2* h0 = (const __half2*)&v0;
        const __half2* h1p = (const __half2*)&v1;
#pragma unroll
        for (int j = 0; j < 4; ++j) {
            float2 f0 = __half22float2(h0[j]);
            float2 f1 = __half22float2(h1p[j]);
            d += qr[2*j]*f0.x + qr[2*j+1]*f0.y;
            d += qr[8+2*j]*f1.x + qr[8+2*j+1]*f1.y;
        }
#pragma unroll
        for (int o = 16; o; o >>= 1) d += __shfl_xor_sync(0xffffffffu, d, o);
        if (lane == 0) {
            sc[kloc] = d;
            g_sc[b*ET_ + uh*512 + kloc] = d;
        }
    }
    flag_bump(&g_fS[b]);
    flag_wait(&g_fS[b], tgt);

    // ---- redundant deterministic max/sum over all 1024 scores ----
    float s0 = __ldcg(&g_sc[b*ET_ + tid]);
    float s1 = __ldcg(&g_sc[b*ET_ + tid + 256]);
    float s2 = __ldcg(&g_sc[b*ET_ + tid + 512]);
    float s3 = __ldcg(&g_sc[b*ET_ + tid + 768]);
    red[tid] = fmaxf(fmaxf(s0, s1), fmaxf(s2, s3));
    __syncthreads();
#pragma unroll
    for (int s = 128; s; s >>= 1) {
        if (tid < s) red[tid] = fmaxf(red[tid], red[tid + s]);
        __syncthreads();
    }
    const float M = red[0];
    __syncthreads();
    red[tid] = __expf(s0 - M) + __expf(s1 - M) + __expf(s2 - M) + __expf(s3 - M);
    __syncthreads();
#pragma unroll
    for (int s = 128; s; s >>= 1) {
        if (tid < s) red[tid] = red[tid] + red[tid + s];
        __syncthreads();
    }
    const float invS = __fdividef(1.f, red[0]);
    __syncthreads();

    // normalized probs for own half
    psm[tid]       = __expf(sc[tid]       - M) * invS;
    psm[tid + 256] = __expf(sc[tid + 256] - M) * invS;
    __syncthreads();

    // ---- pass 2: smem-tiled ctx (32-key x 512-dim fp16 tiles) ----
    // thread owns dims d0, d0+1; loader: key = tid>>3, 8 int4 segs per thread.
    const int d0  = tid * 2;
    const int key = tid >> 3;
    const int seg = tid & 7;
    __half* kb = (__half*)(smemf + TILE_OFF);        // [32][528]
    float cx0 = 0.f, cx1 = 0.f;

    int4 r[8];
    {
        const int4* gp = (const int4*)(hb + (size_t)key*U_);
#pragma unroll
        for (int j = 0; j < 8; ++j) r[j] = __ldcg(gp + j*8 + seg);
    }
#pragma unroll 1
    for (int tt = 0; tt < 16; ++tt) {
        __syncthreads();                             // prev tile compute done
        {
            int4* dst = (int4*)(kb + key*528);
#pragma unroll
            for (int j = 0; j < 8; ++j) dst[j*8 + seg] = r[j];
        }
        if (tt < 15) {
            const int4* gp = (const int4*)(hb + (size_t)((tt+1)*32 + key)*U_);
#pragma unroll
            for (int j = 0; j < 8; ++j) r[j] = __ldcg(gp + j*8 + seg);
        }
        __syncthreads();                             // tile ready
        const float* pt = psm + tt*32;
#pragma unroll
        for (int k = 0; k < 32; ++k) {
            float2 f = __half22float2(*(const __half2*)(kb + k*528 + d0));
            float p = pt[k];
            cx0 += p * f.x;
            cx1 += p * f.y;
        }
    }

    *(float2*)&g_pctx[cta][d0] = make_float2(cx0, cx1);

    // ---- pair merge (second arriver) ----
    __shared__ int s_ticket;
    __syncthreads();
    __threadfence();
    if (tid == 0) s_ticket = (int)atomicAdd(&g_fC[b], 1u);
    __syncthreads();
    if (s_ticket & 1) {
        __threadfence();
        const int partner = cta ^ 1;
        float2 pp;
        pp.x = __ldcg(&g_pctx[partner][d0]);
        pp.y = __ldcg(&g_pctx[partner][d0+1]);
        *(float2*)&g_ctx[b*U_ + d0] = make_float2(cx0 + pp.x, cx1 + pp.y);
    }
    __syncthreads();
}

// ------------------------------- decoder -----------------------------------
__device__ __forceinline__ void decoder_phase(const float* __restrict__ b2v,
                                              const float* __restrict__ bd, int t,
                                              float* __restrict__ out, float* smemf)
{
    const int cta  = blockIdx.x;
    const int tid  = threadIdx.x;
    const int lane = tid & 31;
    const int w    = tid >> 5;
    const int b    = cta >> 1;
    const int uh   = cta & 1;
    const unsigned int tgt = 2u*(t+1);

    float* st = smemf + WSM_FLOATS;         // [1024]

    // gate2 for this (b, half)
    gate_half(1, b, uh, b2v, nullptr, t, g_c2, g_h2);
    flag_bump(&g_fH2[b]);
    flag_wait(&g_fH2[b], tgt);

#pragma unroll
    for (int i = 0; i < 4; ++i) {
        int k = tid + i*256;
        st[k] = (k < 512) ? __ldcg(&g_h2[b*U_ + k]) : g_ctx[b*U_ + k - 512];
    }
    __syncthreads();

    const float4* s4 = (const float4*)st;
#pragma unroll
    for (int vv = 0; vv < 3; ++vv) {
        int vi = w*3 + vv;
        if (vi < 23) {
            int v = uh*23 + vi;
            const float4* wr = (const float4*)(g_WdT + (size_t)v*1024);
            float a = 0.f;
#pragma unroll
            for (int kk = 0; kk < 8; ++kk) {
                float4 wv = wr[lane + kk*32];
                float4 sv = s4[lane + kk*32];
                a += wv.x*sv.x + wv.y*sv.y + wv.z*sv.z + wv.w*sv.w;
            }
#pragma unroll
            for (int o = 16; o; o >>= 1) a += __shfl_xor_sync(0xffffffffu, a, o);
            if (lane == 0) g_logits[b*48 + v] = a + bd[v];
        }
    }

    __shared__ int s_ticket;
    __syncthreads();
    __threadfence();
    if (tid == 0) s_ticket = (int)atomicAdd(&g_fL[b], 1u);
    __syncthreads();

    if ((s_ticket & 1) && w == 0) {
        __threadfence();
        float x0 = (lane      < V_) ? __ldcg(&g_logits[b*48 + lane])      : -INFINITY;
        float x1 = (lane + 32 < V_) ? __ldcg(&g_logits[b*48 + lane + 32]) : -INFINITY;
        float mx = fmaxf(x0, x1);
#pragma unroll
        for (int o = 16; o; o >>= 1) mx = fmaxf(mx, __shfl_xor_sync(0xffffffffu, mx, o));
        float e0 = (lane      < V_) ? __expf(x0 - mx) : 0.f;
        float e1 = (lane + 32 < V_) ? __expf(x1 - mx) : 0.f;
        float ss = e0 + e1;
#pragma unroll
        for (int o = 16; o; o >>= 1) ss += __shfl_xor_sync(0xffffffffu, ss, o);
        float inv = __fdividef(1.f, ss);
        float* op = out + ((size_t)b*T_ + t)*V_;
        if (lane      < V_) op[lane]      = e0*inv;
        if (lane + 32 < V_) op[lane + 32] = e1*inv;
    }
    __syncthreads();
}

// --------------------------- persistent kernel -----------------------------
__global__ void __launch_bounds__(NTHR)
speller_persistent(const float* __restrict__ h,  const float* __restrict__ y,
                   const float* __restrict__ W1, const float* __restrict__ U1,
                   const float* __restrict__ b1, const float* __restrict__ W2,
                   const float* __restrict__ U2, const float* __restrict__ b2,
                   const float* __restrict__ Wd, const float* __restrict__ bd,
                   float* __restrict__ out)
{
    extern __shared__ float smemf[];
    const int tid  = threadIdx.x;
    const int cta  = blockIdx.x;
    const int gtid = cta*NTHR + tid;              // 0..32767

    // ---- prologue ----
    g_h1[gtid]=0.f; g_c1[gtid]=0.f; g_h2[gtid]=0.f; g_c2[gtid]=0.f; g_ctx[gtid]=0.f;
    if (gtid < B_) {
        g_fG1[gtid]=0u; g_fS[gtid]=0u; g_fC[gtid]=0u; g_fH2[gtid]=0u; g_fL[gtid]=0u;
    }

    // weight fold into per-CTA mma slices (tf32-rounded)
    for (size_t idx = gtid; idx < (size_t)2*NCTA*128*128; idx += (size_t)NCTA*NTHR) {
        int layer = (int)(idx >> 21);
        int rem   = (int)(idx & ((1u<<21) - 1));
        int c  = rem >> 14;
        int r2 = rem & 16383;
        int nl = r2 >> 7;
        int kl = r2 & 127;
        int nt = c & 15, ks = c >> 4;
        int n  = nt*128 + nl;
        int kg = ks*128 + kl;
        float v;
        if (layer == 0)
            v = (kg < 512) ? (W1[(size_t)kg*NG_ + n] + U1[(size_t)kg*NG_ + n])
                           : W1[(size_t)(kg+1)*NG_ + n];
        else
            v = (kg < 512) ? W2[(size_t)kg*NG_ + n]
                           : U2[(size_t)(kg-512)*NG_ + n];
        g_WtA[idx] = tf32r(v);
    }
    if (gtid < NG_) g_w1y[gtid] = W1[(size_t)512*NG_ + gtid];
    for (int idx = gtid; idx < V_*1024; idx += NCTA*NTHR)
        g_WdT[idx] = Wd[(size_t)(idx & 1023)*V_ + (idx >> 10)];
    {
        const float2* h2p = (const float2*)h;
        __half2* hhp = (__half2*)g_hh;
        const size_t n2 = (size_t)B_*ET_*U_/2;
        for (size_t i = gtid; i < n2; i += (size_t)NCTA*NTHR)
            hhp[i] = __float22half2_rn(h2p[i]);
    }
    grid_barrier();

    // copy this CTA's weight slices to persistent smem (pad 128->132)
    for (int i = tid; i < 2*128*128; i += NTHR) {
        int layer = i >> 14;
        int nl = (i >> 7) & 127;
        int kl = i & 127;
        smemf[layer*(128*132) + nl*132 + kl] =
            g_WtA[((size_t)layer*NCTA + cta)*16384 + nl*128 + kl];
    }
    __syncthreads();

    // ---- 256 decode steps ----
    for (int t = 0; t < T_; ++t) {
        mma_phase(0, smemf);
        grid_barrier();
        attn_phase(b1, y, t, smemf);
        grid_barrier();
        mma_phase(1, smemf);
        grid_barrier();
        decoder_phase(b2, bd, t, out, smemf);
        // no barrier: next mma1 writes g_Zp[0]; decoder reads g_Zp[1], and the
        // post-mma1 barrier orders decoder(t) before attn(t+1)'s partial reads.
    }
}

// ------------------------------- launcher ----------------------------------
extern "C" void kernel_launch(void* const* d_in, const int* in_sizes, int n_in,
                              void* d_out, int out_size)
{
    (void)in_sizes; (void)n_in; (void)out_size;
    const float* h  = (const float*)d_in[0];
    const float* y  = (const float*)d_in[1];
    const float* W1 = (const float*)d_in[2];
    const float* U1 = (const float*)d_in[3];
    const float* b1 = (const float*)d_in[4];
    const float* W2 = (const float*)d_in[5];
    const float* U2 = (const float*)d_in[6];
    const float* b2 = (const float*)d_in[7];
    const float* Wd = (const float*)d_in[8];
    const float* bd = (const float*)d_in[9];
    float* out = (float*)d_out;

    cudaFuncSetAttribute(speller_persistent,
                         cudaFuncAttributeMaxDynamicSharedMemorySize, SMEM_BYTES);
    speller_persistent<<<NCTA, NTHR, SMEM_BYTES>>>(h, y, W1, U1, b1, W2, U2, b2,
                                                   Wd, bd, out);
}

// round 10
// speedup vs baseline: 2.7379x; 1.2158x over previous
#include <cuda_runtime.h>
#include <cuda_fp16.h>
#include <math.h>

#define B_   64
#define T_   256
#define ET_  1024
#define U_   512
#define V_   46
#define NG_  2048
#define NCTA 128
#define NTHR 256

// ------------------------- persistent device state -------------------------
__device__ float g_h1[B_*U_];
__device__ float g_c1[B_*U_];
__device__ float g_h2[B_*U_];
__device__ float g_c2[B_*U_];
__device__ float g_ctx[B_*U_];

__device__ __half g_hh[(size_t)B_*ET_*U_];          // 67 MB fp16 copy of h

// per-CTA mma weight slices: [layer][cta][n_local 128][k_local 128], tf32-rounded
__device__ float g_WtA[(size_t)2*NCTA*128*128];
__device__ float g_w1y[NG_];
__device__ float g_WdT[V_*1024];

__device__ float g_Zp[2][8][B_][NG_];               // partials per layer/ksplit
__device__ float g_sc[B_*ET_];                      // raw attention scores
__device__ float g_pctx[NCTA][U_];                  // partial ctx
__device__ float g_logits[B_*48];

__device__ unsigned int g_fG1[B_];                  // gate1 halves done
__device__ unsigned int g_fS[B_];                   // score halves done
__device__ unsigned int g_fC[B_];                   // ctx merge ticket
__device__ unsigned int g_fH2[B_];                  // gate2 halves done
__device__ unsigned int g_fL[B_];                   // logits merge ticket
__device__ unsigned int g_bar_count = 0;
__device__ unsigned int g_bar_gen   = 0;

// smem layout (floats): [0, 33792) persistent weights (2 x 128 x 132)
//   scratch base (WSM_FLOATS):
//     mma:      Asm 64x132 = 8448
//     attn:     sc[512] psm[512] red[256]  then TILE at +1280: 8448 (32x528 half)
//     decoder:  st[1024]
#define WSM_FLOATS   (2*128*132)
#define TILE_OFF     (WSM_FLOATS + 1280)
#define SMEM_FLOATS  (TILE_OFF + 8448)
#define SMEM_BYTES   (SMEM_FLOATS * 4)

// ------------------------------ small helpers ------------------------------
__device__ __forceinline__ float tf32r(float x) {
    unsigned int r;
    asm("cvt.rna.tf32.f32 %0, %1;" : "=r"(r) : "f"(x));
    return __uint_as_float(r);
}
__device__ __forceinline__ void mma_tf32(float& c0, float& c1, float& c2, float& c3,
                                         float a0, float a1, float a2, float a3,
                                         float b0, float b1) {
    asm("mma.sync.aligned.m16n8k8.row.col.f32.tf32.tf32.f32 "
        "{%0,%1,%2,%3}, {%4,%5,%6,%7}, {%8,%9}, {%0,%1,%2,%3};"
        : "+f"(c0), "+f"(c1), "+f"(c2), "+f"(c3)
        : "r"(__float_as_uint(a0)), "r"(__float_as_uint(a1)),
          "r"(__float_as_uint(a2)), "r"(__float_as_uint(a3)),
          "r"(__float_as_uint(b0)), "r"(__float_as_uint(b1)));
}
__device__ __forceinline__ float fsig(float x)  { return __fdividef(1.f, 1.f + __expf(-x)); }
__device__ __forceinline__ float ftanh(float x) { return __fdividef(2.f, 1.f + __expf(-2.f*x)) - 1.f; }

// dot of q-slice (16 floats) with one key's 16 fp16 dims packed in two int4
__device__ __forceinline__ float dot16(const float* qr, int4 v0, int4 v1) {
    const __half2* h0 = (const __half2*)&v0;
    const __half2* h1 = (const __half2*)&v1;
    float d = 0.f;
#pragma unroll
    for (int j = 0; j < 4; ++j) {
        float2 f0 = __half22float2(h0[j]);
        float2 f1 = __half22float2(h1[j]);
        d += qr[2*j]*f0.x + qr[2*j+1]*f0.y;
        d += qr[8+2*j]*f1.x + qr[8+2*j+1]*f1.y;
    }
    return d;
}

// ------------------------------ grid barrier -------------------------------
__device__ __forceinline__ void grid_barrier()
{
    __syncthreads();
    if (threadIdx.x == 0) {
        unsigned int gen = *(volatile unsigned int*)&g_bar_gen;
        __threadfence();
        unsigned int ticket = atomicAdd(&g_bar_count, 1u);
        if (ticket == gridDim.x - 1) {
            atomicExch(&g_bar_count, 0u);
            __threadfence();
            *(volatile unsigned int*)&g_bar_gen = gen + 1u;
        } else {
            while (*(volatile unsigned int*)&g_bar_gen == gen) { __nanosleep(64); }
        }
        __threadfence();
    }
    __syncthreads();
}

__device__ __forceinline__ void flag_bump(unsigned int* f)
{
    __syncthreads();
    __threadfence();
    if (threadIdx.x == 0) atomicAdd(f, 1u);
    __syncthreads();
}
__device__ __forceinline__ void flag_wait(unsigned int* f, unsigned int target)
{
    if (threadIdx.x == 0) {
        while (*(volatile unsigned int*)f < target) { __nanosleep(32); }
        __threadfence();
    }
    __syncthreads();
}

// ----------------------------- tensor-core GEMM ----------------------------
// CTA = (nt = cta&15, ks = cta>>4). Computes partial z[layer] for
// cols nt*128..+127, k-range ks*128..+127 over all 64 batch rows.
__device__ __forceinline__ void mma_phase(int layer, float* smemf)
{
    const int cta = blockIdx.x;
    const int tid = threadIdx.x;
    const int nt = cta & 15, ks = cta >> 4;
    const int kg0 = ks * 128;

    const float* __restrict__ SA = layer ? g_ctx : g_h1;
    const float* __restrict__ SB = layer ? g_h2  : g_ctx;
    const float* __restrict__ S  = (kg0 < 512) ? (SA + kg0) : (SB + (kg0 - 512));

    float* Asm = smemf + WSM_FLOATS;                 // [64][132]
    const float* Wl = smemf + layer * (128*132);     // [128 n][132 k]

    // stage A slice: row r (=b), cols qd*32..+31
    {
        const int r  = tid >> 2;
        const int qd = tid & 3;
        const float* src = S + (size_t)r * U_ + qd * 32;
        float* dst = Asm + r * 132 + qd * 32;
#pragma unroll
        for (int j = 0; j < 8; ++j) {
            float4 v = *(const float4*)(src + j * 4);
            dst[j*4 + 0] = tf32r(v.x);
            dst[j*4 + 1] = tf32r(v.y);
            dst[j*4 + 2] = tf32r(v.z);
            dst[j*4 + 3] = tf32r(v.w);
        }
    }
    __syncthreads();

    const int w    = tid >> 5;
    const int lane = tid & 31;
    const int g    = lane >> 2;
    const int l4   = lane & 3;
    const int mt   = w >> 1;             // 0..3
    const int nh   = w & 1;              // 0..1
    const int m0   = mt * 16;

    float c[8][4];
#pragma unroll
    for (int ti = 0; ti < 8; ++ti)
#pragma unroll
        for (int q = 0; q < 4; ++q) c[ti][q] = 0.f;

    const float* Ar0 = Asm + (m0 + g) * 132;
    const float* Ar1 = Ar0 + 8 * 132;

#pragma unroll
    for (int kt = 0; kt < 16; ++kt) {
        const int kq = kt * 8 + l4;
        float a0 = Ar0[kq];
        float a1 = Ar1[kq];
        float a2 = Ar0[kq + 4];
        float a3 = Ar1[kq + 4];
#pragma unroll
        for (int ti = 0; ti < 8; ++ti) {
            const float* Wn = Wl + (nh*64 + ti*8 + g) * 132;
            float b0 = Wn[kq];
            float b1 = Wn[kq + 4];
            mma_tf32(c[ti][0], c[ti][1], c[ti][2], c[ti][3], a0, a1, a2, a3, b0, b1);
        }
    }

    // write partials
    float* zp = &g_Zp[layer][ks][0][0];
#pragma unroll
    for (int ti = 0; ti < 8; ++ti) {
        int nb = nt*128 + nh*64 + ti*8 + 2*l4;
        int r0 = m0 + g;
        *(float2*)(zp + (size_t)r0*NG_ + nb)     = make_float2(c[ti][0], c[ti][1]);
        *(float2*)(zp + (size_t)(r0+8)*NG_ + nb) = make_float2(c[ti][2], c[ti][3]);
    }
    __syncthreads();
}

// ---------------- LSTM gate for one (b, u-half): 256 u's ------------------
__device__ __forceinline__ void gate_half(int layer, int b, int uh,
                                          const float* __restrict__ bias,
                                          const float* __restrict__ y, int t,
                                          float* __restrict__ cS, float* __restrict__ hS)
{
    const int u = uh*256 + threadIdx.x;
    float z0=0.f, z1=0.f, z2=0.f, z3=0.f;
#pragma unroll
    for (int p = 0; p < 8; ++p) {
        const float* zb = &g_Zp[layer][p][b][0];
        z0 += zb[u]; z1 += zb[512+u]; z2 += zb[1024+u]; z3 += zb[1536+u];
    }
    z0 += bias[u]; z1 += bias[512+u]; z2 += bias[1024+u]; z3 += bias[1536+u];
    if (layer == 0) {
        float yv = y[b*T_ + t];
        z0 += yv*g_w1y[u]; z1 += yv*g_w1y[512+u];
        z2 += yv*g_w1y[1024+u]; z3 += yv*g_w1y[1536+u];
    }
    float si = fsig(z0), sf = fsig(z1), tg = ftanh(z2), so = fsig(z3);
    float cn = sf * cS[b*U_ + u] + si * tg;
    cS[b*U_ + u] = cn;
    hS[b*U_ + u] = so * ftanh(cn);
}

// ------------------------- attention (two-pass) ----------------------------
__device__ __forceinline__ void attn_phase(const float* __restrict__ b1v,
                                           const float* __restrict__ y, int t,
                                           float* smemf)
{
    const int cta  = blockIdx.x;
    const int tid  = threadIdx.x;
    const int lane = tid & 31;
    const int w    = tid >> 5;
    const int b    = cta >> 1;
    const int uh   = cta & 1;
    const unsigned int tgt = 2u*(t+1);

    float* sc  = smemf + WSM_FLOATS;        // [512] own-half scores
    float* psm = sc + 512;                  // [512] normalized probs
    float* red = psm + 512;                 // [256] reduction scratch

    // ---- gate1 for this (b, half) ----
    gate_half(0, b, uh, b1v, y, t, g_c1, g_h1);
    flag_bump(&g_fG1[b]);
    flag_wait(&g_fG1[b], tgt);

    // ---- q slice: 16 floats at lane*16 ----
    float qr[16];
    {
        const float* qp = g_h1 + b*U_ + lane*16;
#pragma unroll
        for (int j = 0; j < 4; ++j) {
            float4 v = __ldcg((const float4*)(qp + j*4));
            qr[j*4+0]=v.x; qr[j*4+1]=v.y; qr[j*4+2]=v.z; qr[j*4+3]=v.w;
        }
    }

    // ---- pass 1: scores, 4 keys per iteration (ILP on loads + shfl chains) ----
    const __half* hb = g_hh + ((size_t)(b*ET_ + uh*512))*U_;
#pragma unroll 1
    for (int ii = 0; ii < 16; ++ii) {
        const int kloc = w*64 + ii*4;
        const int4* p0 = (const int4*)(hb + (size_t)(kloc+0)*U_ + lane*16);
        const int4* p1 = (const int4*)(hb + (size_t)(kloc+1)*U_ + lane*16);
        const int4* p2 = (const int4*)(hb + (size_t)(kloc+2)*U_ + lane*16);
        const int4* p3 = (const int4*)(hb + (size_t)(kloc+3)*U_ + lane*16);
        int4 a0 = __ldcg(p0), a1 = __ldcg(p0+1);
        int4 b0 = __ldcg(p1), b1x = __ldcg(p1+1);
        int4 c0 = __ldcg(p2), c1 = __ldcg(p2+1);
        int4 d0v = __ldcg(p3), d1 = __ldcg(p3+1);

        float d0 = dot16(qr, a0, a1);
        float d1x = dot16(qr, b0, b1x);
        float d2 = dot16(qr, c0, c1);
        float d3 = dot16(qr, d0v, d1);
#pragma unroll
        for (int o = 16; o; o >>= 1) {
            d0  += __shfl_xor_sync(0xffffffffu, d0,  o);
            d1x += __shfl_xor_sync(0xffffffffu, d1x, o);
            d2  += __shfl_xor_sync(0xffffffffu, d2,  o);
            d3  += __shfl_xor_sync(0xffffffffu, d3,  o);
        }
        if (lane == 0) {
            sc[kloc+0] = d0;  sc[kloc+1] = d1x;
            sc[kloc+2] = d2;  sc[kloc+3] = d3;
            float* gs = &g_sc[b*ET_ + uh*512 + kloc];
            gs[0] = d0; gs[1] = d1x; gs[2] = d2; gs[3] = d3;
        }
    }
    flag_bump(&g_fS[b]);
    flag_wait(&g_fS[b], tgt);

    // ---- deterministic softmax stats (warp-shfl two-stage) ----
    float s0 = __ldcg(&g_sc[b*ET_ + tid]);
    float s1 = __ldcg(&g_sc[b*ET_ + tid + 256]);
    float s2 = __ldcg(&g_sc[b*ET_ + tid + 512]);
    float s3 = __ldcg(&g_sc[b*ET_ + tid + 768]);
    {
        float mloc = fmaxf(fmaxf(s0, s1), fmaxf(s2, s3));
#pragma unroll
        for (int o = 16; o; o >>= 1) mloc = fmaxf(mloc, __shfl_xor_sync(0xffffffffu, mloc, o));
        if (lane == 0) red[w] = mloc;
    }
    __syncthreads();
    float M = red[0];
#pragma unroll
    for (int p = 1; p < 8; ++p) M = fmaxf(M, red[p]);
    {
        float eloc = __expf(s0 - M) + __expf(s1 - M) + __expf(s2 - M) + __expf(s3 - M);
#pragma unroll
        for (int o = 16; o; o >>= 1) eloc += __shfl_xor_sync(0xffffffffu, eloc, o);
        if (lane == 0) red[8 + w] = eloc;
    }
    __syncthreads();
    float Ssum = red[8];
#pragma unroll
    for (int p = 9; p < 16; ++p) Ssum += red[p];
    const float invS = __fdividef(1.f, Ssum);

    // normalized probs for own half
    psm[tid]       = __expf(sc[tid]       - M) * invS;
    psm[tid + 256] = __expf(sc[tid + 256] - M) * invS;
    __syncthreads();

    // ---- pass 2: smem-tiled ctx (32-key x 512-dim fp16 tiles) ----
    // thread owns dims d0, d0+1; loader: key = tid>>3, 8 int4 segs per thread.
    const int d0  = tid * 2;
    const int key = tid >> 3;
    const int seg = tid & 7;
    __half* kb = (__half*)(smemf + TILE_OFF);        // [32][528]
    float cx0 = 0.f, cx1 = 0.f, cy0 = 0.f, cy1 = 0.f;

    int4 r[8];
    {
        const int4* gp = (const int4*)(hb + (size_t)key*U_);
#pragma unroll
        for (int j = 0; j < 8; ++j) r[j] = __ldcg(gp + j*8 + seg);
    }
#pragma unroll 1
    for (int tt = 0; tt < 16; ++tt) {
        __syncthreads();                             // prev tile compute done
        {
            int4* dst = (int4*)(kb + key*528);
#pragma unroll
            for (int j = 0; j < 8; ++j) dst[j*8 + seg] = r[j];
        }
        if (tt < 15) {
            const int4* gp = (const int4*)(hb + (size_t)((tt+1)*32 + key)*U_);
#pragma unroll
            for (int j = 0; j < 8; ++j) r[j] = __ldcg(gp + j*8 + seg);
        }
        __syncthreads();                             // tile ready
        const float* pt = psm + tt*32;
#pragma unroll
        for (int k = 0; k < 32; k += 2) {
            float2 f0 = __half22float2(*(const __half2*)(kb + k*528 + d0));
            float2 f1 = __half22float2(*(const __half2*)(kb + (k+1)*528 + d0));
            float p0 = pt[k], p1 = pt[k+1];
            cx0 += p0 * f0.x;  cx1 += p0 * f0.y;
            cy0 += p1 * f1.x;  cy1 += p1 * f1.y;
        }
    }
    cx0 += cy0;  cx1 += cy1;

    *(float2*)&g_pctx[cta][d0] = make_float2(cx0, cx1);

    // ---- pair merge (second arriver) ----
    __shared__ int s_ticket;
    __syncthreads();
    __threadfence();
    if (tid == 0) s_ticket = (int)atomicAdd(&g_fC[b], 1u);
    __syncthreads();
    if (s_ticket & 1) {
        __threadfence();
        const int partner = cta ^ 1;
        float2 pp;
        pp.x = __ldcg(&g_pctx[partner][d0]);
        pp.y = __ldcg(&g_pctx[partner][d0+1]);
        *(float2*)&g_ctx[b*U_ + d0] = make_float2(cx0 + pp.x, cx1 + pp.y);
    }
    __syncthreads();
}

// ------------------------------- decoder -----------------------------------
__device__ __forceinline__ void decoder_phase(const float* __restrict__ b2v,
                                              const float* __restrict__ bd, int t,
                                              float* __restrict__ out, float* smemf)
{
    const int cta  = blockIdx.x;
    const int tid  = threadIdx.x;
    const int lane = tid & 31;
    const int w    = tid >> 5;
    const int b    = cta >> 1;
    const int uh   = cta & 1;
    const unsigned int tgt = 2u*(t+1);

    float* st = smemf + WSM_FLOATS;         // [1024]

    // gate2 for this (b, half)
    gate_half(1, b, uh, b2v, nullptr, t, g_c2, g_h2);
    flag_bump(&g_fH2[b]);
    flag_wait(&g_fH2[b], tgt);

#pragma unroll
    for (int i = 0; i < 4; ++i) {
        int k = tid + i*256;
        st[k] = (k < 512) ? __ldcg(&g_h2[b*U_ + k]) : g_ctx[b*U_ + k - 512];
    }
    __syncthreads();

    const float4* s4 = (const float4*)st;
#pragma unroll
    for (int vv = 0; vv < 3; ++vv) {
        int vi = w*3 + vv;
        if (vi < 23) {
            int v = uh*23 + vi;
            const float4* wr = (const float4*)(g_WdT + (size_t)v*1024);
            float a = 0.f;
#pragma unroll
            for (int kk = 0; kk < 8; ++kk) {
                float4 wv = wr[lane + kk*32];
                float4 sv = s4[lane + kk*32];
                a += wv.x*sv.x + wv.y*sv.y + wv.z*sv.z + wv.w*sv.w;
            }
#pragma unroll
            for (int o = 16; o; o >>= 1) a += __shfl_xor_sync(0xffffffffu, a, o);
            if (lane == 0) g_logits[b*48 + v] = a + bd[v];
        }
    }

    __shared__ int s_ticket;
    __syncthreads();
    __threadfence();
    if (tid == 0) s_ticket = (int)atomicAdd(&g_fL[b], 1u);
    __syncthreads();

    if ((s_ticket & 1) && w == 0) {
        __threadfence();
        float x0 = (lane      < V_) ? __ldcg(&g_logits[b*48 + lane])      : -INFINITY;
        float x1 = (lane + 32 < V_) ? __ldcg(&g_logits[b*48 + lane + 32]) : -INFINITY;
        float mx = fmaxf(x0, x1);
#pragma unroll
        for (int o = 16; o; o >>= 1) mx = fmaxf(mx, __shfl_xor_sync(0xffffffffu, mx, o));
        float e0 = (lane      < V_) ? __expf(x0 - mx) : 0.f;
        float e1 = (lane + 32 < V_) ? __expf(x1 - mx) : 0.f;
        float ss = e0 + e1;
#pragma unroll
        for (int o = 16; o; o >>= 1) ss += __shfl_xor_sync(0xffffffffu, ss, o);
        float inv = __fdividef(1.f, ss);
        float* op = out + ((size_t)b*T_ + t)*V_;
        if (lane      < V_) op[lane]      = e0*inv;
        if (lane + 32 < V_) op[lane + 32] = e1*inv;
    }
    __syncthreads();
}

// --------------------------- persistent kernel -----------------------------
__global__ void __launch_bounds__(NTHR)
speller_persistent(const float* __restrict__ h,  const float* __restrict__ y,
                   const float* __restrict__ W1, const float* __restrict__ U1,
                   const float* __restrict__ b1, const float* __restrict__ W2,
                   const float* __restrict__ U2, const float* __restrict__ b2,
                   const float* __restrict__ Wd, const float* __restrict__ bd,
                   float* __restrict__ out)
{
    extern __shared__ float smemf[];
    const int tid  = threadIdx.x;
    const int cta  = blockIdx.x;
    const int gtid = cta*NTHR + tid;              // 0..32767

    // ---- prologue ----
    g_h1[gtid]=0.f; g_c1[gtid]=0.f; g_h2[gtid]=0.f; g_c2[gtid]=0.f; g_ctx[gtid]=0.f;
    if (gtid < B_) {
        g_fG1[gtid]=0u; g_fS[gtid]=0u; g_fC[gtid]=0u; g_fH2[gtid]=0u; g_fL[gtid]=0u;
    }

    // weight fold into per-CTA mma slices (tf32-rounded)
    for (size_t idx = gtid; idx < (size_t)2*NCTA*128*128; idx += (size_t)NCTA*NTHR) {
        int layer = (int)(idx >> 21);
        int rem   = (int)(idx & ((1u<<21) - 1));
        int c  = rem >> 14;
        int r2 = rem & 16383;
        int nl = r2 >> 7;
        int kl = r2 & 127;
        int nt = c & 15, ks = c >> 4;
        int n  = nt*128 + nl;
        int kg = ks*128 + kl;
        float v;
        if (layer == 0)
            v = (kg < 512) ? (W1[(size_t)kg*NG_ + n] + U1[(size_t)kg*NG_ + n])
                           : W1[(size_t)(kg+1)*NG_ + n];
        else
            v = (kg < 512) ? W2[(size_t)kg*NG_ + n]
                           : U2[(size_t)(kg-512)*NG_ + n];
        g_WtA[idx] = tf32r(v);
    }
    if (gtid < NG_) g_w1y[gtid] = W1[(size_t)512*NG_ + gtid];
    for (int idx = gtid; idx < V_*1024; idx += NCTA*NTHR)
        g_WdT[idx] = Wd[(size_t)(idx & 1023)*V_ + (idx >> 10)];
    {
        const float2* h2p = (const float2*)h;
        __half2* hhp = (__half2*)g_hh;
        const size_t n2 = (size_t)B_*ET_*U_/2;
        for (size_t i = gtid; i < n2; i += (size_t)NCTA*NTHR)
            hhp[i] = __float22half2_rn(h2p[i]);
    }
    grid_barrier();

    // copy this CTA's weight slices to persistent smem (pad 128->132)
    for (int i = tid; i < 2*128*128; i += NTHR) {
        int layer = i >> 14;
        int nl = (i >> 7) & 127;
        int kl = i & 127;
        smemf[layer*(128*132) + nl*132 + kl] =
            g_WtA[((size_t)layer*NCTA + cta)*16384 + nl*128 + kl];
    }
    __syncthreads();

    // ---- 256 decode steps ----
    for (int t = 0; t < T_; ++t) {
        mma_phase(0, smemf);
        grid_barrier();
        attn_phase(b1, y, t, smemf);
        grid_barrier();
        mma_phase(1, smemf);
        grid_barrier();
        decoder_phase(b2, bd, t, out, smemf);
        // no barrier: next mma1 writes g_Zp[0]; decoder reads g_Zp[1], and the
        // post-mma1 barrier orders decoder(t) before attn(t+1)'s partial reads.
    }
}

// ------------------------------- launcher ----------------------------------
extern "C" void kernel_launch(void* const* d_in, const int* in_sizes, int n_in,
                              void* d_out, int out_size)
{
    (void)in_sizes; (void)n_in; (void)out_size;
    const float* h  = (const float*)d_in[0];
    const float* y  = (const float*)d_in[1];
    const float* W1 = (const float*)d_in[2];
    const float* U1 = (const float*)d_in[3];
    const float* b1 = (const float*)d_in[4];
    const float* W2 = (const float*)d_in[5];
    const float* U2 = (const float*)d_in[6];
    const float* b2 = (const float*)d_in[7];
    const float* Wd = (const float*)d_in[8];
    const float* bd = (const float*)d_in[9];
    float* out = (float*)d_out;

    cudaFuncSetAttribute(speller_persistent,
                         cudaFuncAttributeMaxDynamicSharedMemorySize, SMEM_BYTES);
    speller_persistent<<<NCTA, NTHR, SMEM_BYTES>>>(h, y, W1, U1, b1, W2, U2, b2,
                                                   Wd, bd, out);
}